// round 1
// baseline (speedup 1.0000x reference)
#include <cuda_runtime.h>
#include <math.h>

#define T_TOK 65536
#define P_DIM 512
#define D_DIM 1024

// ---------------- scratch (device globals; no allocation allowed) ----------------
__device__ float g_patches[(size_t)T_TOK * P_DIM];   // 134 MB
__device__ float g_wtop0[T_TOK];
__device__ unsigned char g_mask[T_TOK];
__device__ unsigned char g_w[T_TOK];
__device__ int g_list[T_TOK];
__device__ int g_listcnt;
__device__ int g_histA[768];      // level0: 3 x 256
__device__ int g_histB[768];      // level1: 3 x 256
__device__ int g_histC[384];      // level2: 3 x 128
__device__ unsigned g_pre[3];
__device__ int g_rem[3];
__device__ int g_nums[3];
__device__ int g_cnt[3];
__device__ float g_ms_part[128 * 4 * 512];  // per-block partials: [blk][bag,e0,e1,e2][p]
__device__ float g_bag[512];
__device__ float g_ms[3][512];
__device__ float g_acc_part[512 * 512];     // gemm2 partials: [rowtile][p]
__device__ float g_acc[512];

// ---------------- zero accumulators (every launch; graph-replay safe) ----------------
__global__ void zero_kernel() {
    int i = blockIdx.x * blockDim.x + threadIdx.x;
    int stride = gridDim.x * blockDim.x;
    for (int idx = i; idx < 512 * 512; idx += stride) g_acc_part[idx] = 0.f;
    if (i < 768) { g_histA[i] = 0; g_histB[i] = 0; }
    if (i < 384) g_histC[i] = 0;
    if (i < 3) g_pre[i] = 0u;
}

// ---------------- GEMM1: patches = tanh(X @ W_t1), 65536x1024 @ 1024x512 ----------------
__global__ __launch_bounds__(256) void gemm1_kernel(const float* __restrict__ A,
                                                    const float* __restrict__ B) {
    const int K = D_DIM, N = P_DIM;
    __shared__ float As[2][8][128];
    __shared__ float Bs[2][8][128];
    int tid = threadIdx.x;
    const float* Ab = A + (size_t)blockIdx.y * 128 * K;
    const float* Bb = B + blockIdx.x * 128;
    int aRow = tid >> 1, aCol = (tid & 1) << 2;
    int bRow = tid >> 5, bCol = (tid & 31) << 2;
    int ty = tid >> 4, tx = tid & 15;
    float acc[8][8];
#pragma unroll
    for (int i = 0; i < 8; i++)
#pragma unroll
        for (int j = 0; j < 8; j++) acc[i][j] = 0.f;

    float4 a4 = *reinterpret_cast<const float4*>(Ab + (size_t)aRow * K + aCol);
    float4 b4 = *reinterpret_cast<const float4*>(Bb + (size_t)bRow * N + bCol);
    As[0][aCol + 0][aRow] = a4.x; As[0][aCol + 1][aRow] = a4.y;
    As[0][aCol + 2][aRow] = a4.z; As[0][aCol + 3][aRow] = a4.w;
    *reinterpret_cast<float4*>(&Bs[0][bRow][bCol]) = b4;
    __syncthreads();
    int buf = 0;
    for (int k0 = 8; k0 <= K; k0 += 8) {
        if (k0 < K) {
            a4 = *reinterpret_cast<const float4*>(Ab + (size_t)aRow * K + k0 + aCol);
            b4 = *reinterpret_cast<const float4*>(Bb + (size_t)(k0 + bRow) * N + bCol);
        }
#pragma unroll
        for (int k = 0; k < 8; k++) {
            float ra[8], rb[8];
            *reinterpret_cast<float4*>(&ra[0]) = *reinterpret_cast<float4*>(&As[buf][k][ty * 8]);
            *reinterpret_cast<float4*>(&ra[4]) = *reinterpret_cast<float4*>(&As[buf][k][ty * 8 + 4]);
            *reinterpret_cast<float4*>(&rb[0]) = *reinterpret_cast<float4*>(&Bs[buf][k][tx * 8]);
            *reinterpret_cast<float4*>(&rb[4]) = *reinterpret_cast<float4*>(&Bs[buf][k][tx * 8 + 4]);
#pragma unroll
            for (int i = 0; i < 8; i++)
#pragma unroll
                for (int j = 0; j < 8; j++) acc[i][j] += ra[i] * rb[j];
        }
        if (k0 < K) {
            buf ^= 1;
            As[buf][aCol + 0][aRow] = a4.x; As[buf][aCol + 1][aRow] = a4.y;
            As[buf][aCol + 2][aRow] = a4.z; As[buf][aCol + 3][aRow] = a4.w;
            *reinterpret_cast<float4*>(&Bs[buf][bRow][bCol]) = b4;
            __syncthreads();
        }
    }
    size_t row0 = (size_t)blockIdx.y * 128 + ty * 8;
    int col0 = blockIdx.x * 128 + tx * 8;
#pragma unroll
    for (int i = 0; i < 8; i++) {
        float* Crow = g_patches + (row0 + i) * N + col0;
#pragma unroll
        for (int j = 0; j < 8; j++) Crow[j] = tanhf(acc[i][j]);
    }
}

// ---------------- router: logits for 3 gates, w_top0, masks ----------------
__global__ __launch_bounds__(256) void router_kernel(const float* __restrict__ Wg0,
                                                     const float* __restrict__ Wg1,
                                                     const float* __restrict__ Wg2,
                                                     float* __restrict__ out_rl) {
    __shared__ float sW[6][512];
    int tid = threadIdx.x;
    for (int p = tid; p < 512; p += 256) {
        sW[0][p] = Wg0[2 * p]; sW[1][p] = Wg0[2 * p + 1];
        sW[2][p] = Wg1[2 * p]; sW[3][p] = Wg1[2 * p + 1];
        sW[4][p] = Wg2[2 * p]; sW[5][p] = Wg2[2 * p + 1];
    }
    __syncthreads();
    int warp = tid >> 5, lane = tid & 31;
    int t = blockIdx.x * 8 + warp;
    const float* row = g_patches + (size_t)t * 512;
    float a0 = 0, b0 = 0, a1 = 0, b1 = 0, a2 = 0, b2 = 0;
    for (int k = lane; k < 512; k += 32) {
        float v = row[k];
        a0 += v * sW[0][k]; b0 += v * sW[1][k];
        a1 += v * sW[2][k]; b1 += v * sW[3][k];
        a2 += v * sW[4][k]; b2 += v * sW[5][k];
    }
#pragma unroll
    for (int o = 16; o; o >>= 1) {
        a0 += __shfl_xor_sync(0xffffffffu, a0, o);
        b0 += __shfl_xor_sync(0xffffffffu, b0, o);
        a1 += __shfl_xor_sync(0xffffffffu, a1, o);
        b1 += __shfl_xor_sync(0xffffffffu, b1, o);
        a2 += __shfl_xor_sync(0xffffffffu, a2, o);
        b2 += __shfl_xor_sync(0xffffffffu, b2, o);
    }
    if (lane == 0) {
        out_rl[2 * t] = a0;
        out_rl[2 * t + 1] = b0;
        float wt = 1.0f / (1.0f + expf(-fabsf(a0 - b0)));   // max of 2-way softmax
        g_wtop0[t] = wt;
        int mk = (b0 > a0 ? 1 : 0) | (b1 > a1 ? 2 : 0) | (b2 > a2 ? 4 : 0);
        g_mask[t] = (unsigned char)mk;
    }
}

// ---------------- radix threshold search over w_top0 bits ----------------
__global__ __launch_bounds__(256) void hist_kernel(int level) {
    __shared__ int sh[768];
    int nbins = (level == 2) ? 128 : 256;
    int shift = (level == 0) ? 15 : (level == 1) ? 7 : 0;
    int hs = (level == 0) ? 23 : (level == 1) ? 15 : 7;
    int* hist = (level == 0) ? g_histA : (level == 1) ? g_histB : g_histC;
    int tid = threadIdx.x;
    int nb3 = 3 * nbins;
    for (int i = tid; i < nb3; i += 256) sh[i] = 0;
    __syncthreads();
    unsigned p0 = g_pre[0] >> hs, p1 = g_pre[1] >> hs, p2 = g_pre[2] >> hs;
    int stride = gridDim.x * 256;
    for (int t = blockIdx.x * 256 + tid; t < T_TOK; t += stride) {
        unsigned u = __float_as_uint(g_wtop0[t]);
        unsigned v = u - 0x3F000000u;
        if (v > 0x7FFFFFu) v = 0x7FFFFFu;
        int mk = g_mask[t];
        unsigned vh = v >> hs;
        int bin = (int)((v >> shift) & (unsigned)(nbins - 1));
        if ((mk & 1) && vh == p0) atomicAdd(&sh[bin], 1);
        if ((mk & 2) && vh == p1) atomicAdd(&sh[nbins + bin], 1);
        if ((mk & 4) && vh == p2) atomicAdd(&sh[2 * nbins + bin], 1);
    }
    __syncthreads();
    for (int i = tid; i < nb3; i += 256)
        if (sh[i]) atomicAdd(&hist[i], sh[i]);
}

__global__ void find_kernel(int level) {
    __shared__ int sh[768];
    int nbins = (level == 2) ? 128 : 256;
    int shift = (level == 0) ? 15 : (level == 1) ? 7 : 0;
    const int* hist = (level == 0) ? g_histA : (level == 1) ? g_histB : g_histC;
    int tid = threadIdx.x;
    for (int i = tid; i < 3 * nbins; i += blockDim.x) sh[i] = hist[i];
    __syncthreads();
    if (tid < 3) {
        int e = tid;
        unsigned prefix;
        int rem;
        if (level == 0) {
            int tot = 0;
            for (int b = 0; b < nbins; b++) tot += sh[e * nbins + b];
            const float fr = (e == 1) ? 0.5f : 0.25f;
            int nums = (int)floorf((float)tot * fr);
            if (nums == 0) nums = tot;
            g_cnt[e] = tot;
            g_nums[e] = nums;
            prefix = 0u;
            rem = nums;
        } else {
            prefix = g_pre[e];
            rem = g_rem[e];
        }
        int acc = 0;
        int b;
        for (b = nbins - 1; b >= 0; b--) {
            int c = sh[e * nbins + b];
            if (acc + c >= rem) break;
            acc += c;
        }
        if (b < 0) b = 0;
        rem -= acc;
        prefix |= ((unsigned)b) << shift;
        g_pre[e] = prefix;
        g_rem[e] = rem;
    }
}

// ---------------- ordered selection + stable tie-break + deterministic compaction ----------------
__global__ __launch_bounds__(1024) void select_kernel() {
    __shared__ int warpcnt[32][4];
    int tid = threadIdx.x, wid = tid >> 5, lane = tid & 31;
    unsigned pre[3];
    int tt[3];
#pragma unroll
    for (int e = 0; e < 3; e++) { pre[e] = g_pre[e]; tt[e] = g_rem[e]; }
    int base[4] = {0, 0, 0, 0};
    for (int start = 0; start < T_TOK; start += 1024) {
        int t = start + tid;
        unsigned v = __float_as_uint(g_wtop0[t]) - 0x3F000000u;
        if (v > 0x7FFFFFu) v = 0x7FFFFFu;
        int mk = g_mask[t];
        int r[3];
        bool gt[3], eq[3];
#pragma unroll
        for (int e = 0; e < 3; e++) {
            bool m = ((mk >> e) & 1) != 0;
            eq[e] = m && (v == pre[e]);
            gt[e] = m && (v > pre[e]);
            unsigned bal = __ballot_sync(0xffffffffu, eq[e]);
            r[e] = __popc(bal & ((1u << lane) - 1u));
            if (lane == 0) warpcnt[wid][e] = __popc(bal);
        }
        __syncthreads();
        int wb[3] = {0, 0, 0}, ct[3] = {0, 0, 0};
        for (int w = 0; w < 32; w++) {
#pragma unroll
            for (int e = 0; e < 3; e++) {
                int c = warpcnt[w][e];
                if (w < wid) wb[e] += c;
                ct[e] += c;
            }
        }
        int selbits = 0;
#pragma unroll
        for (int e = 0; e < 3; e++) {
            int rank = base[e] + wb[e] + r[e];
            if (gt[e] || (eq[e] && rank < tt[e])) selbits |= 1 << e;
        }
        g_w[t] = (unsigned char)selbits;
        int wmul = __popc((unsigned)selbits);
        bool has = wmul > 0;
        unsigned bal3 = __ballot_sync(0xffffffffu, has);
        int r3 = __popc(bal3 & ((1u << lane) - 1u));
        if (lane == 0) warpcnt[wid][3] = __popc(bal3);
        __syncthreads();
        int wb3 = 0, ct3 = 0;
        for (int w = 0; w < 32; w++) {
            int c = warpcnt[w][3];
            if (w < wid) wb3 += c;
            ct3 += c;
        }
        if (has) g_list[base[3] + wb3 + r3] = t | (wmul << 20);
        base[0] += ct[0]; base[1] += ct[1]; base[2] += ct[2]; base[3] += ct3;
        __syncthreads();
    }
    if (tid == 0) g_listcnt = base[3];
}

// ---------------- weighted column sums of patches (bag + 3 expert sums), deterministic ----------------
__global__ __launch_bounds__(512) void msum_kernel() {
    int blk = blockIdx.x;          // 128 blocks
    int p = threadIdx.x;           // 512 columns
    int t0 = blk * 512;
    float sb = 0.f, s0 = 0.f, s1 = 0.f, s2 = 0.f;
    for (int i = 0; i < 512; i++) {
        int t = t0 + i;
        float v = g_patches[(size_t)t * 512 + p];
        sb += v;
        int w = g_w[t];
        if (w & 1) s0 += v;
        if (w & 2) s1 += v;
        if (w & 4) s2 += v;
    }
    float* base = &g_ms_part[blk * 4 * 512];
    base[p] = sb;
    base[512 + p] = s0;
    base[1024 + p] = s1;
    base[1536 + p] = s2;
}

__global__ __launch_bounds__(512) void msum_reduce_kernel() {
    int p = threadIdx.x;
    float sb = 0.f, s0 = 0.f, s1 = 0.f, s2 = 0.f;
    for (int b = 0; b < 128; b++) {
        const float* base = &g_ms_part[b * 4 * 512];
        sb += base[p];
        s0 += base[512 + p];
        s1 += base[1024 + p];
        s2 += base[1536 + p];
    }
    g_bag[p] = sb;
    g_ms[0][p] = s0;
    g_ms[1][p] = s1;
    g_ms[2][p] = s2;
}

// ---------------- block reduction helper (512 threads) ----------------
__device__ float blockReduce512(float v, float* red) {
    int tid = threadIdx.x;
    red[tid] = v;
    __syncthreads();
    for (int s = 256; s > 0; s >>= 1) {
        if (tid < s) red[tid] += red[tid + s];
        __syncthreads();
    }
    float r = red[0];
    __syncthreads();
    return r;
}

// ---------------- trans1 outputs + expert CE losses + distribute ----------------
__global__ __launch_bounds__(512) void finalize1_kernel(const float* __restrict__ W_cls1,
                                                        const float* __restrict__ W_clf,
                                                        float* __restrict__ out) {
    __shared__ float red[512];
    int p = threadIdx.x;
    float bagmean = g_bag[p] * (1.0f / 65536.0f);
    float yl0 = blockReduce512(bagmean * W_cls1[2 * p], red);
    float yl1 = blockReduce512(bagmean * W_cls1[2 * p + 1], red);
    float l[3][3];
    for (int e = 0; e < 3; e++) {
        int nd = g_nums[e];
        if (nd < 1) nd = 1;
        float mf = g_ms[e][p] / (float)nd;
        for (int c = 0; c < 3; c++)
            l[e][c] = blockReduce512(mf * W_clf[(e * 512 + p) * 3 + c], red);
    }
    if (p == 0) {
        out[3] = yl0;
        out[4] = yl1;
        float m = fmaxf(yl0, yl1);
        float e0 = expf(yl0 - m), e1 = expf(yl1 - m);
        float s = e0 + e1;
        out[5] = e0 / s;
        out[6] = e1 / s;
        out[7] = (yl1 > yl0) ? 1.f : 0.f;
        float loss = 0.f;
        for (int e = 0; e < 2; e++) {
            float m3 = fmaxf(l[e][0], fmaxf(l[e][1], l[e][2]));
            float lse = logf(expf(l[e][0] - m3) + expf(l[e][1] - m3) + expf(l[e][2] - m3));
            loss += -(l[e][e] - m3 - lse);
        }
        out[131080] = loss;
        out[131081] = 65536.f;
        out[131082] = (float)g_nums[0];
        out[131083] = (float)g_nums[1];
        out[131084] = (float)g_nums[2];
    }
}

// ---------------- GEMM2: weighted sum of tanh(patches[sel] @ W_a1) ----------------
__global__ __launch_bounds__(256) void gemm2_kernel(const float* __restrict__ Bmat) {
    const int K = P_DIM, N = P_DIM;
    int cnt = g_listcnt;
    int row0 = blockIdx.y * 128;
    if (row0 >= cnt) return;   // partials pre-zeroed
    __shared__ float As[2][8][128];
    __shared__ float Bs[2][8][128];
    __shared__ int sTok[128];
    __shared__ float sWt[128];
    __shared__ float sRed[16][128];
    int tid = threadIdx.x;
    if (tid < 128) {
        int r = row0 + tid;
        if (r < cnt) {
            int ent = g_list[r];
            sTok[tid] = ent & 0xFFFFF;
            sWt[tid] = (float)(ent >> 20);
        } else {
            sTok[tid] = 0;
            sWt[tid] = 0.f;
        }
    }
    __syncthreads();
    const float* Bb = Bmat + blockIdx.x * 128;
    int aRow = tid >> 1, aCol = (tid & 1) << 2;
    int bRow = tid >> 5, bCol = (tid & 31) << 2;
    int ty = tid >> 4, tx = tid & 15;
    int tokA = sTok[aRow];
    const float* Arow = g_patches + (size_t)tokA * K;
    float acc[8][8];
#pragma unroll
    for (int i = 0; i < 8; i++)
#pragma unroll
        for (int j = 0; j < 8; j++) acc[i][j] = 0.f;

    float4 a4 = *reinterpret_cast<const float4*>(Arow + aCol);
    float4 b4 = *reinterpret_cast<const float4*>(Bb + (size_t)bRow * N + bCol);
    As[0][aCol + 0][aRow] = a4.x; As[0][aCol + 1][aRow] = a4.y;
    As[0][aCol + 2][aRow] = a4.z; As[0][aCol + 3][aRow] = a4.w;
    *reinterpret_cast<float4*>(&Bs[0][bRow][bCol]) = b4;
    __syncthreads();
    int buf = 0;
    for (int k0 = 8; k0 <= K; k0 += 8) {
        if (k0 < K) {
            a4 = *reinterpret_cast<const float4*>(Arow + k0 + aCol);
            b4 = *reinterpret_cast<const float4*>(Bb + (size_t)(k0 + bRow) * N + bCol);
        }
#pragma unroll
        for (int k = 0; k < 8; k++) {
            float ra[8], rb[8];
            *reinterpret_cast<float4*>(&ra[0]) = *reinterpret_cast<float4*>(&As[buf][k][ty * 8]);
            *reinterpret_cast<float4*>(&ra[4]) = *reinterpret_cast<float4*>(&As[buf][k][ty * 8 + 4]);
            *reinterpret_cast<float4*>(&rb[0]) = *reinterpret_cast<float4*>(&Bs[buf][k][tx * 8]);
            *reinterpret_cast<float4*>(&rb[4]) = *reinterpret_cast<float4*>(&Bs[buf][k][tx * 8 + 4]);
#pragma unroll
            for (int i = 0; i < 8; i++)
#pragma unroll
                for (int j = 0; j < 8; j++) acc[i][j] += ra[i] * rb[j];
        }
        if (k0 < K) {
            buf ^= 1;
            As[buf][aCol + 0][aRow] = a4.x; As[buf][aCol + 1][aRow] = a4.y;
            As[buf][aCol + 2][aRow] = a4.z; As[buf][aCol + 3][aRow] = a4.w;
            *reinterpret_cast<float4*>(&Bs[buf][bRow][bCol]) = b4;
            __syncthreads();
        }
    }
    float csum[8];
#pragma unroll
    for (int j = 0; j < 8; j++) csum[j] = 0.f;
#pragma unroll
    for (int i = 0; i < 8; i++) {
        float w = sWt[ty * 8 + i];
        if (w != 0.f) {
#pragma unroll
            for (int j = 0; j < 8; j++) csum[j] += w * tanhf(acc[i][j]);
        }
    }
#pragma unroll
    for (int j = 0; j < 8; j++) sRed[ty][tx * 8 + j] = csum[j];
    __syncthreads();
    if (tid < 128) {
        float s = 0.f;
#pragma unroll
        for (int r = 0; r < 16; r++) s += sRed[r][tid];
        g_acc_part[blockIdx.y * 512 + blockIdx.x * 128 + tid] = s;
    }
}

__global__ __launch_bounds__(512) void acc_reduce_kernel() {
    int p = threadIdx.x;
    float s = 0.f;
    for (int rt = 0; rt < 512; rt++) s += g_acc_part[rt * 512 + p];
    g_acc[p] = s;
}

// ---------------- aggregated classifier outputs ----------------
__global__ __launch_bounds__(512) void finalize2_kernel(const float* __restrict__ W_acls,
                                                        float* __restrict__ out) {
    __shared__ float red[512];
    int p = threadIdx.x;
    float tn = (float)(g_nums[0] + g_nums[1] + g_nums[2]);
    float d = fmaxf(tn, 1.0f);
    float a = g_acc[p] / d;
    float el0 = blockReduce512(a * W_acls[2 * p], red);
    float el1 = blockReduce512(a * W_acls[2 * p + 1], red);
    if (p == 0) {
        out[0] = el0;
        out[1] = el1;
        out[2] = (el1 > el0) ? 1.f : 0.f;
    }
}

// ---------------- launch ----------------
extern "C" void kernel_launch(void* const* d_in, const int* in_sizes, int n_in,
                              void* d_out, int out_size) {
    (void)in_sizes; (void)n_in; (void)out_size;
    const float* hidden = (const float*)d_in[0];
    const float* W_t1   = (const float*)d_in[1];
    const float* W_cls1 = (const float*)d_in[2];
    const float* Wg0    = (const float*)d_in[3];
    const float* Wg1    = (const float*)d_in[4];
    const float* Wg2    = (const float*)d_in[5];
    const float* W_clf  = (const float*)d_in[6];
    const float* W_a1   = (const float*)d_in[7];
    const float* W_acls = (const float*)d_in[8];
    float* out = (float*)d_out;

    zero_kernel<<<512, 256>>>();

    dim3 g1(4, 512);
    gemm1_kernel<<<g1, 256>>>(hidden, W_t1);

    router_kernel<<<8192, 256>>>(Wg0, Wg1, Wg2, out + 8);

    hist_kernel<<<64, 256>>>(0);
    find_kernel<<<1, 256>>>(0);
    hist_kernel<<<64, 256>>>(1);
    find_kernel<<<1, 256>>>(1);
    hist_kernel<<<64, 256>>>(2);
    find_kernel<<<1, 256>>>(2);

    select_kernel<<<1, 1024>>>();

    msum_kernel<<<128, 512>>>();
    msum_reduce_kernel<<<1, 512>>>();
    finalize1_kernel<<<1, 512>>>(W_cls1, W_clf, out);

    dim3 g2(4, 512);
    gemm2_kernel<<<g2, 256>>>(W_a1);
    acc_reduce_kernel<<<1, 512>>>();
    finalize2_kernel<<<1, 512>>>(W_acls, out);
}

// round 6
// speedup vs baseline: 1.0899x; 1.0899x over previous
#include <cuda_runtime.h>
#include <cuda_bf16.h>
#include <math.h>
#include <stdint.h>

#define T_TOK 65536
#define P_DIM 512
#define D_DIM 1024

// ---------------- scratch (device globals; no allocation allowed) ----------------
__device__ float g_patches[(size_t)T_TOK * P_DIM];   // 134 MB
__device__ float g_wtop0[T_TOK];
__device__ unsigned char g_mask[T_TOK];
__device__ unsigned char g_w[T_TOK];
__device__ int g_list[T_TOK];
__device__ int g_listcnt;
__device__ int g_histA[768];      // level0: 3 x 256
__device__ int g_histB[768];      // level1: 3 x 256
__device__ int g_histC[384];      // level2: 3 x 128
__device__ unsigned g_pre[3];
__device__ int g_rem[3];
__device__ int g_nums[3];
__device__ int g_cnt[3];
__device__ float g_ms_part[128 * 4 * 512];  // per-block partials: [blk][bag,e0,e1,e2][p]
__device__ float g_bag[512];
__device__ float g_ms[3][512];
__device__ float g_acc_part[512 * 512];     // gemm2 partials: [rowtile][p]
__device__ float g_acc[512];

// ---------------- packed f32x2 helpers (SASS FFMA2 — only reachable via PTX) ----------------
__device__ __forceinline__ unsigned long long ffma2(unsigned long long a,
                                                    unsigned long long b,
                                                    unsigned long long c) {
    unsigned long long d;
    asm("fma.rn.f32x2 %0, %1, %2, %3;" : "=l"(d) : "l"(a), "l"(b), "l"(c));
    return d;
}
__device__ __forceinline__ unsigned long long bcast2(float x) {
    unsigned long long r;
    asm("mov.b64 %0, {%1, %1};" : "=l"(r) : "f"(x));
    return r;
}
__device__ __forceinline__ void unpack2(unsigned long long v, float& lo, float& hi) {
    asm("mov.b64 {%0, %1}, %2;" : "=f"(lo), "=f"(hi) : "l"(v));
}

// ---------------- zero accumulators (every launch; graph-replay safe) ----------------
__global__ void zero_kernel() {
    int i = blockIdx.x * blockDim.x + threadIdx.x;
    int stride = gridDim.x * blockDim.x;
    for (int idx = i; idx < 512 * 512; idx += stride) g_acc_part[idx] = 0.f;
    if (i < 768) { g_histA[i] = 0; g_histB[i] = 0; }
    if (i < 384) g_histC[i] = 0;
    if (i < 3) g_pre[i] = 0u;
}

// ---------------- GEMM1: patches = tanh(X @ W_t1), 65536x1024 @ 1024x512, FFMA2 ----------------
__global__ __launch_bounds__(256) void gemm1_kernel(const float* __restrict__ A,
                                                    const float* __restrict__ B) {
    const int K = D_DIM, N = P_DIM;
    __shared__ __align__(16) float As[2][8][128];
    __shared__ __align__(16) float Bs[2][8][128];
    int tid = threadIdx.x;
    const float* Ab = A + (size_t)blockIdx.y * 128 * K;
    const float* Bb = B + blockIdx.x * 128;
    int aRow = tid >> 1, aCol = (tid & 1) << 2;
    int bRow = tid >> 5, bCol = (tid & 31) << 2;
    int ty = tid >> 4, tx = tid & 15;
    unsigned long long acc2[8][4];
#pragma unroll
    for (int i = 0; i < 8; i++)
#pragma unroll
        for (int j = 0; j < 4; j++) acc2[i][j] = 0ull;

    float4 a4 = *reinterpret_cast<const float4*>(Ab + (size_t)aRow * K + aCol);
    float4 b4 = *reinterpret_cast<const float4*>(Bb + (size_t)bRow * N + bCol);
    As[0][aCol + 0][aRow] = a4.x; As[0][aCol + 1][aRow] = a4.y;
    As[0][aCol + 2][aRow] = a4.z; As[0][aCol + 3][aRow] = a4.w;
    *reinterpret_cast<float4*>(&Bs[0][bRow][bCol]) = b4;
    __syncthreads();
    int buf = 0;
    for (int k0 = 8; k0 <= K; k0 += 8) {
        if (k0 < K) {
            a4 = *reinterpret_cast<const float4*>(Ab + (size_t)aRow * K + k0 + aCol);
            b4 = *reinterpret_cast<const float4*>(Bb + (size_t)(k0 + bRow) * N + bCol);
        }
#pragma unroll
        for (int k = 0; k < 8; k++) {
            float ra[8];
            unsigned long long rb2[4];
            *reinterpret_cast<float4*>(&ra[0]) = *reinterpret_cast<float4*>(&As[buf][k][ty * 8]);
            *reinterpret_cast<float4*>(&ra[4]) = *reinterpret_cast<float4*>(&As[buf][k][ty * 8 + 4]);
            const unsigned long long* bp =
                reinterpret_cast<const unsigned long long*>(&Bs[buf][k][tx * 8]);
            rb2[0] = bp[0]; rb2[1] = bp[1]; rb2[2] = bp[2]; rb2[3] = bp[3];
#pragma unroll
            for (int i = 0; i < 8; i++) {
                unsigned long long ai = bcast2(ra[i]);
#pragma unroll
                for (int j = 0; j < 4; j++) acc2[i][j] = ffma2(ai, rb2[j], acc2[i][j]);
            }
        }
        if (k0 < K) {
            buf ^= 1;
            As[buf][aCol + 0][aRow] = a4.x; As[buf][aCol + 1][aRow] = a4.y;
            As[buf][aCol + 2][aRow] = a4.z; As[buf][aCol + 3][aRow] = a4.w;
            *reinterpret_cast<float4*>(&Bs[buf][bRow][bCol]) = b4;
            __syncthreads();
        }
    }
    size_t row0 = (size_t)blockIdx.y * 128 + ty * 8;
    int col0 = blockIdx.x * 128 + tx * 8;
#pragma unroll
    for (int i = 0; i < 8; i++) {
        float* Crow = g_patches + (row0 + i) * N + col0;
        float c[8];
#pragma unroll
        for (int j = 0; j < 4; j++) unpack2(acc2[i][j], c[2 * j], c[2 * j + 1]);
        float4 o0, o1;
        o0.x = tanhf(c[0]); o0.y = tanhf(c[1]); o0.z = tanhf(c[2]); o0.w = tanhf(c[3]);
        o1.x = tanhf(c[4]); o1.y = tanhf(c[5]); o1.z = tanhf(c[6]); o1.w = tanhf(c[7]);
        *reinterpret_cast<float4*>(Crow) = o0;
        *reinterpret_cast<float4*>(Crow + 4) = o1;
    }
}

// ---------------- router: logits for 3 gates, w_top0, masks ----------------
__global__ __launch_bounds__(256) void router_kernel(const float* __restrict__ Wg0,
                                                     const float* __restrict__ Wg1,
                                                     const float* __restrict__ Wg2,
                                                     float* __restrict__ out_rl) {
    __shared__ float sW[6][512];
    int tid = threadIdx.x;
    for (int p = tid; p < 512; p += 256) {
        sW[0][p] = Wg0[2 * p]; sW[1][p] = Wg0[2 * p + 1];
        sW[2][p] = Wg1[2 * p]; sW[3][p] = Wg1[2 * p + 1];
        sW[4][p] = Wg2[2 * p]; sW[5][p] = Wg2[2 * p + 1];
    }
    __syncthreads();
    int warp = tid >> 5, lane = tid & 31;
    int t = blockIdx.x * 8 + warp;
    const float* row = g_patches + (size_t)t * 512;
    float a0 = 0, b0 = 0, a1 = 0, b1 = 0, a2 = 0, b2 = 0;
    for (int k = lane; k < 512; k += 32) {
        float v = row[k];
        a0 += v * sW[0][k]; b0 += v * sW[1][k];
        a1 += v * sW[2][k]; b1 += v * sW[3][k];
        a2 += v * sW[4][k]; b2 += v * sW[5][k];
    }
#pragma unroll
    for (int o = 16; o; o >>= 1) {
        a0 += __shfl_xor_sync(0xffffffffu, a0, o);
        b0 += __shfl_xor_sync(0xffffffffu, b0, o);
        a1 += __shfl_xor_sync(0xffffffffu, a1, o);
        b1 += __shfl_xor_sync(0xffffffffu, b1, o);
        a2 += __shfl_xor_sync(0xffffffffu, a2, o);
        b2 += __shfl_xor_sync(0xffffffffu, b2, o);
    }
    if (lane == 0) {
        out_rl[2 * t] = a0;
        out_rl[2 * t + 1] = b0;
        float wt = 1.0f / (1.0f + expf(-fabsf(a0 - b0)));   // max of 2-way softmax
        g_wtop0[t] = wt;
        int mk = (b0 > a0 ? 1 : 0) | (b1 > a1 ? 2 : 0) | (b2 > a2 ? 4 : 0);
        g_mask[t] = (unsigned char)mk;
    }
}

// ---------------- radix threshold search over w_top0 bits ----------------
__global__ __launch_bounds__(256) void hist_kernel(int level) {
    __shared__ int sh[768];
    int nbins = (level == 2) ? 128 : 256;
    int shift = (level == 0) ? 15 : (level == 1) ? 7 : 0;
    int hs = (level == 0) ? 23 : (level == 1) ? 15 : 7;
    int* hist = (level == 0) ? g_histA : (level == 1) ? g_histB : g_histC;
    int tid = threadIdx.x;
    int nb3 = 3 * nbins;
    for (int i = tid; i < nb3; i += 256) sh[i] = 0;
    __syncthreads();
    unsigned p0 = g_pre[0] >> hs, p1 = g_pre[1] >> hs, p2 = g_pre[2] >> hs;
    int stride = gridDim.x * 256;
    for (int t = blockIdx.x * 256 + tid; t < T_TOK; t += stride) {
        unsigned u = __float_as_uint(g_wtop0[t]);
        unsigned v = u - 0x3F000000u;
        if (v > 0x7FFFFFu) v = 0x7FFFFFu;
        int mk = g_mask[t];
        unsigned vh = v >> hs;
        int bin = (int)((v >> shift) & (unsigned)(nbins - 1));
        if ((mk & 1) && vh == p0) atomicAdd(&sh[bin], 1);
        if ((mk & 2) && vh == p1) atomicAdd(&sh[nbins + bin], 1);
        if ((mk & 4) && vh == p2) atomicAdd(&sh[2 * nbins + bin], 1);
    }
    __syncthreads();
    for (int i = tid; i < nb3; i += 256)
        if (sh[i]) atomicAdd(&hist[i], sh[i]);
}

__global__ void find_kernel(int level) {
    __shared__ int sh[768];
    int nbins = (level == 2) ? 128 : 256;
    int shift = (level == 0) ? 15 : (level == 1) ? 7 : 0;
    const int* hist = (level == 0) ? g_histA : (level == 1) ? g_histB : g_histC;
    int tid = threadIdx.x;
    for (int i = tid; i < 3 * nbins; i += blockDim.x) sh[i] = hist[i];
    __syncthreads();
    if (tid < 3) {
        int e = tid;
        unsigned prefix;
        int rem;
        if (level == 0) {
            int tot = 0;
            for (int b = 0; b < nbins; b++) tot += sh[e * nbins + b];
            const float fr = (e == 1) ? 0.5f : 0.25f;
            int nums = (int)floorf((float)tot * fr);
            if (nums == 0) nums = tot;
            g_cnt[e] = tot;
            g_nums[e] = nums;
            prefix = 0u;
            rem = nums;
        } else {
            prefix = g_pre[e];
            rem = g_rem[e];
        }
        int acc = 0;
        int b;
        for (b = nbins - 1; b >= 0; b--) {
            int c = sh[e * nbins + b];
            if (acc + c >= rem) break;
            acc += c;
        }
        if (b < 0) b = 0;
        rem -= acc;
        prefix |= ((unsigned)b) << shift;
        g_pre[e] = prefix;
        g_rem[e] = rem;
    }
}

// ---------------- ordered selection + stable tie-break + deterministic compaction ----------------
__global__ __launch_bounds__(1024) void select_kernel() {
    __shared__ int warpcnt[32][4];
    int tid = threadIdx.x, wid = tid >> 5, lane = tid & 31;
    unsigned pre[3];
    int tt[3];
#pragma unroll
    for (int e = 0; e < 3; e++) { pre[e] = g_pre[e]; tt[e] = g_rem[e]; }
    int base[4] = {0, 0, 0, 0};
    for (int start = 0; start < T_TOK; start += 1024) {
        int t = start + tid;
        unsigned v = __float_as_uint(g_wtop0[t]) - 0x3F000000u;
        if (v > 0x7FFFFFu) v = 0x7FFFFFu;
        int mk = g_mask[t];
        int r[3];
        bool gt[3], eq[3];
#pragma unroll
        for (int e = 0; e < 3; e++) {
            bool m = ((mk >> e) & 1) != 0;
            eq[e] = m && (v == pre[e]);
            gt[e] = m && (v > pre[e]);
            unsigned bal = __ballot_sync(0xffffffffu, eq[e]);
            r[e] = __popc(bal & ((1u << lane) - 1u));
            if (lane == 0) warpcnt[wid][e] = __popc(bal);
        }
        __syncthreads();
        int wb[3] = {0, 0, 0}, ct[3] = {0, 0, 0};
        for (int w = 0; w < 32; w++) {
#pragma unroll
            for (int e = 0; e < 3; e++) {
                int c = warpcnt[w][e];
                if (w < wid) wb[e] += c;
                ct[e] += c;
            }
        }
        int selbits = 0;
#pragma unroll
        for (int e = 0; e < 3; e++) {
            int rank = base[e] + wb[e] + r[e];
            if (gt[e] || (eq[e] && rank < tt[e])) selbits |= 1 << e;
        }
        g_w[t] = (unsigned char)selbits;
        int wmul = __popc((unsigned)selbits);
        bool has = wmul > 0;
        unsigned bal3 = __ballot_sync(0xffffffffu, has);
        int r3 = __popc(bal3 & ((1u << lane) - 1u));
        if (lane == 0) warpcnt[wid][3] = __popc(bal3);
        __syncthreads();
        int wb3 = 0, ct3 = 0;
        for (int w = 0; w < 32; w++) {
            int c = warpcnt[w][3];
            if (w < wid) wb3 += c;
            ct3 += c;
        }
        if (has) g_list[base[3] + wb3 + r3] = t | (wmul << 20);
        base[0] += ct[0]; base[1] += ct[1]; base[2] += ct[2]; base[3] += ct3;
        __syncthreads();
    }
    if (tid == 0) g_listcnt = base[3];
}

// ---------------- weighted column sums of patches (bag + 3 expert sums), deterministic ----------------
__global__ __launch_bounds__(512) void msum_kernel() {
    int blk = blockIdx.x;          // 128 blocks
    int p = threadIdx.x;           // 512 columns
    int t0 = blk * 512;
    float sb = 0.f, s0 = 0.f, s1 = 0.f, s2 = 0.f;
    for (int i = 0; i < 512; i++) {
        int t = t0 + i;
        float v = g_patches[(size_t)t * 512 + p];
        sb += v;
        int w = g_w[t];
        if (w & 1) s0 += v;
        if (w & 2) s1 += v;
        if (w & 4) s2 += v;
    }
    float* base = &g_ms_part[blk * 4 * 512];
    base[p] = sb;
    base[512 + p] = s0;
    base[1024 + p] = s1;
    base[1536 + p] = s2;
}

__global__ __launch_bounds__(512) void msum_reduce_kernel() {
    int p = threadIdx.x;
    float sb = 0.f, s0 = 0.f, s1 = 0.f, s2 = 0.f;
    for (int b = 0; b < 128; b++) {
        const float* base = &g_ms_part[b * 4 * 512];
        sb += base[p];
        s0 += base[512 + p];
        s1 += base[1024 + p];
        s2 += base[1536 + p];
    }
    g_bag[p] = sb;
    g_ms[0][p] = s0;
    g_ms[1][p] = s1;
    g_ms[2][p] = s2;
}

// ---------------- block reduction helper (512 threads) ----------------
__device__ float blockReduce512(float v, float* red) {
    int tid = threadIdx.x;
    red[tid] = v;
    __syncthreads();
    for (int s = 256; s > 0; s >>= 1) {
        if (tid < s) red[tid] += red[tid + s];
        __syncthreads();
    }
    float r = red[0];
    __syncthreads();
    return r;
}

// ---------------- trans1 outputs + expert CE losses + distribute ----------------
__global__ __launch_bounds__(512) void finalize1_kernel(const float* __restrict__ W_cls1,
                                                        const float* __restrict__ W_clf,
                                                        float* __restrict__ out) {
    __shared__ float red[512];
    int p = threadIdx.x;
    float bagmean = g_bag[p] * (1.0f / 65536.0f);
    float yl0 = blockReduce512(bagmean * W_cls1[2 * p], red);
    float yl1 = blockReduce512(bagmean * W_cls1[2 * p + 1], red);
    float l[3][3];
    for (int e = 0; e < 3; e++) {
        int nd = g_nums[e];
        if (nd < 1) nd = 1;
        float mf = g_ms[e][p] / (float)nd;
        for (int c = 0; c < 3; c++)
            l[e][c] = blockReduce512(mf * W_clf[(e * 512 + p) * 3 + c], red);
    }
    if (p == 0) {
        out[3] = yl0;
        out[4] = yl1;
        float m = fmaxf(yl0, yl1);
        float e0 = expf(yl0 - m), e1 = expf(yl1 - m);
        float s = e0 + e1;
        out[5] = e0 / s;
        out[6] = e1 / s;
        out[7] = (yl1 > yl0) ? 1.f : 0.f;
        float loss = 0.f;
        for (int e = 0; e < 2; e++) {
            float m3 = fmaxf(l[e][0], fmaxf(l[e][1], l[e][2]));
            float lse = logf(expf(l[e][0] - m3) + expf(l[e][1] - m3) + expf(l[e][2] - m3));
            loss += -(l[e][e] - m3 - lse);
        }
        out[131080] = loss;
        out[131081] = 65536.f;
        out[131082] = (float)g_nums[0];
        out[131083] = (float)g_nums[1];
        out[131084] = (float)g_nums[2];
    }
}

// ---------------- GEMM2: weighted sum of tanh(patches[sel] @ W_a1), FFMA2 ----------------
__global__ __launch_bounds__(256) void gemm2_kernel(const float* __restrict__ Bmat) {
    const int K = P_DIM, N = P_DIM;
    int cnt = g_listcnt;
    int row0 = blockIdx.y * 128;
    if (row0 >= cnt) return;   // partials pre-zeroed
    __shared__ __align__(16) float As[2][8][128];
    __shared__ __align__(16) float Bs[2][8][128];
    __shared__ int sTok[128];
    __shared__ float sWt[128];
    __shared__ float sRed[16][128];
    int tid = threadIdx.x;
    if (tid < 128) {
        int r = row0 + tid;
        if (r < cnt) {
            int ent = g_list[r];
            sTok[tid] = ent & 0xFFFFF;
            sWt[tid] = (float)(ent >> 20);
        } else {
            sTok[tid] = 0;
            sWt[tid] = 0.f;
        }
    }
    __syncthreads();
    const float* Bb = Bmat + blockIdx.x * 128;
    int aRow = tid >> 1, aCol = (tid & 1) << 2;
    int bRow = tid >> 5, bCol = (tid & 31) << 2;
    int ty = tid >> 4, tx = tid & 15;
    int tokA = sTok[aRow];
    const float* Arow = g_patches + (size_t)tokA * K;
    unsigned long long acc2[8][4];
#pragma unroll
    for (int i = 0; i < 8; i++)
#pragma unroll
        for (int j = 0; j < 4; j++) acc2[i][j] = 0ull;

    float4 a4 = *reinterpret_cast<const float4*>(Arow + aCol);
    float4 b4 = *reinterpret_cast<const float4*>(Bb + (size_t)bRow * N + bCol);
    As[0][aCol + 0][aRow] = a4.x; As[0][aCol + 1][aRow] = a4.y;
    As[0][aCol + 2][aRow] = a4.z; As[0][aCol + 3][aRow] = a4.w;
    *reinterpret_cast<float4*>(&Bs[0][bRow][bCol]) = b4;
    __syncthreads();
    int buf = 0;
    for (int k0 = 8; k0 <= K; k0 += 8) {
        if (k0 < K) {
            a4 = *reinterpret_cast<const float4*>(Arow + k0 + aCol);
            b4 = *reinterpret_cast<const float4*>(Bb + (size_t)(k0 + bRow) * N + bCol);
        }
#pragma unroll
        for (int k = 0; k < 8; k++) {
            float ra[8];
            unsigned long long rb2[4];
            *reinterpret_cast<float4*>(&ra[0]) = *reinterpret_cast<float4*>(&As[buf][k][ty * 8]);
            *reinterpret_cast<float4*>(&ra[4]) = *reinterpret_cast<float4*>(&As[buf][k][ty * 8 + 4]);
            const unsigned long long* bp =
                reinterpret_cast<const unsigned long long*>(&Bs[buf][k][tx * 8]);
            rb2[0] = bp[0]; rb2[1] = bp[1]; rb2[2] = bp[2]; rb2[3] = bp[3];
#pragma unroll
            for (int i = 0; i < 8; i++) {
                unsigned long long ai = bcast2(ra[i]);
#pragma unroll
                for (int j = 0; j < 4; j++) acc2[i][j] = ffma2(ai, rb2[j], acc2[i][j]);
            }
        }
        if (k0 < K) {
            buf ^= 1;
            As[buf][aCol + 0][aRow] = a4.x; As[buf][aCol + 1][aRow] = a4.y;
            As[buf][aCol + 2][aRow] = a4.z; As[buf][aCol + 3][aRow] = a4.w;
            *reinterpret_cast<float4*>(&Bs[buf][bRow][bCol]) = b4;
            __syncthreads();
        }
    }
    float csum[8];
#pragma unroll
    for (int j = 0; j < 8; j++) csum[j] = 0.f;
#pragma unroll
    for (int i = 0; i < 8; i++) {
        float w = sWt[ty * 8 + i];
        if (w != 0.f) {
            float c[8];
#pragma unroll
            for (int j = 0; j < 4; j++) unpack2(acc2[i][j], c[2 * j], c[2 * j + 1]);
#pragma unroll
            for (int j = 0; j < 8; j++) csum[j] += w * tanhf(c[j]);
        }
    }
#pragma unroll
    for (int j = 0; j < 8; j++) sRed[ty][tx * 8 + j] = csum[j];
    __syncthreads();
    if (tid < 128) {
        float s = 0.f;
#pragma unroll
        for (int r = 0; r < 16; r++) s += sRed[r][tid];
        g_acc_part[blockIdx.y * 512 + blockIdx.x * 128 + tid] = s;
    }
}

__global__ __launch_bounds__(512) void acc_reduce_kernel() {
    int p = threadIdx.x;
    float s = 0.f;
    for (int rt = 0; rt < 512; rt++) s += g_acc_part[rt * 512 + p];
    g_acc[p] = s;
}

// ---------------- aggregated classifier outputs ----------------
__global__ __launch_bounds__(512) void finalize2_kernel(const float* __restrict__ W_acls,
                                                        float* __restrict__ out) {
    __shared__ float red[512];
    int p = threadIdx.x;
    float tn = (float)(g_nums[0] + g_nums[1] + g_nums[2]);
    float d = fmaxf(tn, 1.0f);
    float a = g_acc[p] / d;
    float el0 = blockReduce512(a * W_acls[2 * p], red);
    float el1 = blockReduce512(a * W_acls[2 * p + 1], red);
    if (p == 0) {
        out[0] = el0;
        out[1] = el1;
        out[2] = (el1 > el0) ? 1.f : 0.f;
    }
}

// ---------------- launch ----------------
extern "C" void kernel_launch(void* const* d_in, const int* in_sizes, int n_in,
                              void* d_out, int out_size) {
    (void)in_sizes; (void)n_in; (void)out_size;
    const float* hidden = (const float*)d_in[0];
    const float* W_t1   = (const float*)d_in[1];
    const float* W_cls1 = (const float*)d_in[2];
    const float* Wg0    = (const float*)d_in[3];
    const float* Wg1    = (const float*)d_in[4];
    const float* Wg2    = (const float*)d_in[5];
    const float* W_clf  = (const float*)d_in[6];
    const float* W_a1   = (const float*)d_in[7];
    const float* W_acls = (const float*)d_in[8];
    float* out = (float*)d_out;

    zero_kernel<<<512, 256>>>();

    dim3 g1(4, 512);
    gemm1_kernel<<<g1, 256>>>(hidden, W_t1);

    router_kernel<<<8192, 256>>>(Wg0, Wg1, Wg2, out + 8);

    hist_kernel<<<64, 256>>>(0);
    find_kernel<<<1, 256>>>(0);
    hist_kernel<<<64, 256>>>(1);
    find_kernel<<<1, 256>>>(1);
    hist_kernel<<<64, 256>>>(2);
    find_kernel<<<1, 256>>>(2);

    select_kernel<<<1, 1024>>>();

    msum_kernel<<<128, 512>>>();
    msum_reduce_kernel<<<1, 512>>>();
    finalize1_kernel<<<1, 512>>>(W_cls1, W_clf, out);

    dim3 g2(4, 512);
    gemm2_kernel<<<g2, 256>>>(W_a1);
    acc_reduce_kernel<<<1, 512>>>();
    finalize2_kernel<<<1, 512>>>(W_acls, out);
}

// round 10
// speedup vs baseline: 1.9733x; 1.8104x over previous
#include <cuda_runtime.h>
#include <cuda_bf16.h>
#include <math.h>
#include <stdint.h>

#define T_TOK 65536
#define P_DIM 512
#define D_DIM 1024

// ---------------- scratch (device globals; no allocation allowed) ----------------
__device__ float g_patches[(size_t)T_TOK * P_DIM];   // 134 MB
__device__ __align__(16) unsigned char g_Bsw1[2 * 1024 * 1024];  // gemm1 B: 4bx x 32ch x {hi,lo} x 8KB
__device__ __align__(16) unsigned char g_Bsw2[1024 * 1024];      // gemm2 B: 4bx x 16ch x {hi,lo} x 8KB
__device__ float g_wtop0[T_TOK];
__device__ unsigned char g_mask[T_TOK];
__device__ unsigned char g_w[T_TOK];
__device__ int g_list[T_TOK];
__device__ int g_listcnt;
__device__ int g_histA[768];      // level0: 3 x 256
__device__ int g_histB[768];      // level1: 3 x 256
__device__ int g_histC[384];      // level2: 3 x 128
__device__ unsigned g_pre[3];
__device__ int g_rem[3];
__device__ int g_nums[3];
__device__ int g_cnt[3];
__device__ float g_ms_part[128 * 4 * 512];  // per-block partials: [blk][bag,e0,e1,e2][p]
__device__ float g_bag[512];
__device__ float g_ms[3][512];
__device__ float g_acc_part[512 * 512];     // gemm2 partials: [rowtile][p]
__device__ float g_acc[512];

// ---------------- PTX helpers: ldmatrix + bf16 mma (legal on compute_103) ----------------
__device__ __forceinline__ uint32_t smem_u32(const void* p) {
    uint32_t a;
    asm("{ .reg .u64 t; cvta.to.shared.u64 t, %1; cvt.u32.u64 %0, t; }" : "=r"(a) : "l"(p));
    return a;
}
__device__ __forceinline__ void ldsm4(uint32_t* r, uint32_t addr) {
    asm volatile("ldmatrix.sync.aligned.m8n8.x4.shared.b16 {%0,%1,%2,%3}, [%4];"
                 : "=r"(r[0]), "=r"(r[1]), "=r"(r[2]), "=r"(r[3]) : "r"(addr));
}
__device__ __forceinline__ void ldsm2(uint32_t* r, uint32_t addr) {
    asm volatile("ldmatrix.sync.aligned.m8n8.x2.shared.b16 {%0,%1}, [%2];"
                 : "=r"(r[0]), "=r"(r[1]) : "r"(addr));
}
__device__ __forceinline__ void mma_bf16(float* c, const uint32_t* a, const uint32_t* b) {
    asm volatile("mma.sync.aligned.m16n8k16.row.col.f32.bf16.bf16.f32 "
                 "{%0,%1,%2,%3}, {%4,%5,%6,%7}, {%8,%9}, {%0,%1,%2,%3};"
                 : "+f"(c[0]), "+f"(c[1]), "+f"(c[2]), "+f"(c[3])
                 : "r"(a[0]), "r"(a[1]), "r"(a[2]), "r"(a[3]), "r"(b[0]), "r"(b[1]));
}
__device__ __forceinline__ void cvt_hilo(float4 v, uint2& hi, uint2& lo) {
    __nv_bfloat16 hx = __float2bfloat16(v.x), hy = __float2bfloat16(v.y);
    __nv_bfloat16 hz = __float2bfloat16(v.z), hw = __float2bfloat16(v.w);
    __nv_bfloat16 lx = __float2bfloat16(v.x - __bfloat162float(hx));
    __nv_bfloat16 ly = __float2bfloat16(v.y - __bfloat162float(hy));
    __nv_bfloat16 lz = __float2bfloat16(v.z - __bfloat162float(hz));
    __nv_bfloat16 lw = __float2bfloat16(v.w - __bfloat162float(hw));
    __nv_bfloat162 h01, h23, l01, l23;
    h01.x = hx; h01.y = hy; h23.x = hz; h23.y = hw;
    l01.x = lx; l01.y = ly; l23.x = lz; l23.y = lw;
    hi.x = *(uint32_t*)&h01; hi.y = *(uint32_t*)&h23;
    lo.x = *(uint32_t*)&l01; lo.y = *(uint32_t*)&l23;
}

// ---------------- zero accumulators (every launch; graph-replay safe) ----------------
__global__ void zero_kernel() {
    int i = blockIdx.x * blockDim.x + threadIdx.x;
    int stride = gridDim.x * blockDim.x;
    for (int idx = i; idx < 512 * 512; idx += stride) g_acc_part[idx] = 0.f;
    if (i < 768) { g_histA[i] = 0; g_histB[i] = 0; }
    if (i < 384) g_histC[i] = 0;
    if (i < 3) g_pre[i] = 0u;
}

// ---------------- B prep: W (K x 512) -> pre-swizzled bf16 hi/lo tiles in global ----------------
// dst layout per (bx, chunk, h): 8KB tile, byte = n*64 + ((k>>3 ^ ((n>>1)&3))<<4) + (k&7)*2
__global__ __launch_bounds__(256) void prep_kernel(const float* __restrict__ W, int nchunk, int which) {
    unsigned char* dst = which ? g_Bsw2 : g_Bsw1;
    int idx = blockIdx.x * 256 + threadIdx.x;
    int total = 4 * nchunk * 2 * 128 * 32;
    if (idx >= total) return;
    int k = idx & 31;
    int n = (idx >> 5) & 127;
    int h = (idx >> 12) & 1;
    int rest = idx >> 13;
    int chunk = rest % nchunk;
    int bx = rest / nchunk;
    float w = W[(size_t)(chunk * 32 + k) * 512 + bx * 128 + n];
    __nv_bfloat16 hi = __float2bfloat16(w);
    __nv_bfloat16 v = h ? __float2bfloat16(w - __bfloat162float(hi)) : hi;
    size_t tile = (size_t)(bx * nchunk + chunk) * 2 + h;
    size_t off = tile * 8192 + n * 64 + ((((k >> 3) ^ ((n >> 1) & 3)) << 4)) + (k & 7) * 2;
    *(__nv_bfloat16*)(dst + off) = v;
}

// ---------------- shared mma core macro-ish structure ----------------
// smem per buffer (32KB): Ahi@0, Alo@8192, Bhi@16384, Blo@24576. Double buffered = 64KB.

// ---------------- GEMM1 (mma.sync bf16 hi/lo): patches = tanh(X @ W_t1) ----------------
__global__ __launch_bounds__(256) void gemm1_mma_kernel(const float* __restrict__ A) {
    extern __shared__ __align__(16) char sm[];
    const int tid = threadIdx.x, lane = tid & 31, wid = tid >> 5;
    const int wm = (wid & 1) << 6, wn = (wid >> 1) << 5;
    uint32_t sbase = smem_u32(sm);
    const float* Ab = A + (size_t)blockIdx.y * 128 * D_DIM;
    const uint4* Bg = (const uint4*)g_Bsw1 + (size_t)blockIdx.x * 32 * 1024;

    const int srow = tid >> 1, kq = (tid & 1) << 4;
    uint32_t stoff[4];
#pragma unroll
    for (int jj = 0; jj < 4; jj++) {
        int k0 = kq + jj * 4;
        stoff[jj] = srow * 64 + ((((k0 >> 3) ^ ((srow >> 1) & 3)) << 4)) + (k0 & 7) * 2;
    }

    float acc[4][4][4];
#pragma unroll
    for (int i = 0; i < 4; i++)
#pragma unroll
        for (int j = 0; j < 4; j++)
#pragma unroll
            for (int q = 0; q < 4; q++) acc[i][j][q] = 0.f;

    float4 areg[4];
    uint4 breg[4];
#pragma unroll
    for (int jj = 0; jj < 4; jj++) {
        areg[jj] = *(const float4*)(Ab + (size_t)srow * D_DIM + kq + jj * 4);
        breg[jj] = Bg[jj * 256 + tid];
    }
    // stage chunk 0 into buf 0
    {
        char* base = sm;
#pragma unroll
        for (int jj = 0; jj < 4; jj++) {
            uint2 hi, lo;
            cvt_hilo(areg[jj], hi, lo);
            *(uint2*)(base + stoff[jj]) = hi;
            *(uint2*)(base + 8192 + stoff[jj]) = lo;
            *(uint4*)(base + 16384 + (jj * 256 + tid) * 16) = breg[jj];
        }
    }
    __syncthreads();

    int buf = 0;
    for (int c = 0; c < 32; c++) {
        if (c < 31) {
#pragma unroll
            for (int jj = 0; jj < 4; jj++) {
                areg[jj] = *(const float4*)(Ab + (size_t)srow * D_DIM + (c + 1) * 32 + kq + jj * 4);
                breg[jj] = Bg[(c + 1) * 1024 + jj * 256 + tid];
            }
        }
        uint32_t Ah = sbase + buf * 32768;
        uint32_t Al = Ah + 8192;
        uint32_t Bh = Ah + 16384;
        uint32_t Bl = Ah + 24576;
        const int aw = lane & 7, aq = lane >> 3;
        const int bw = lane & 7, bq = (lane >> 3) & 1;
#pragma unroll
        for (int kk = 0; kk < 2; kk++) {
            uint32_t ahi[4][4], alo[4][4], bhi[4][2], blo[4][2];
            int ag = kk * 2 + (aq >> 1);
#pragma unroll
            for (int i = 0; i < 4; i++) {
                int r = wm + i * 16 + aw + ((aq & 1) << 3);
                uint32_t off = r * 64 + (((ag ^ ((r >> 1) & 3)) << 4));
                ldsm4(ahi[i], Ah + off);
                ldsm4(alo[i], Al + off);
            }
            int bg = kk * 2 + bq;
#pragma unroll
            for (int j = 0; j < 4; j++) {
                int n = wn + j * 8 + bw;
                uint32_t off = n * 64 + (((bg ^ ((n >> 1) & 3)) << 4));
                ldsm2(bhi[j], Bh + off);
                ldsm2(blo[j], Bl + off);
            }
#pragma unroll
            for (int i = 0; i < 4; i++)
#pragma unroll
                for (int j = 0; j < 4; j++) {
                    mma_bf16(acc[i][j], ahi[i], bhi[j]);
                    mma_bf16(acc[i][j], alo[i], bhi[j]);
                    mma_bf16(acc[i][j], ahi[i], blo[j]);
                }
        }
        if (c < 31) {
            char* base = sm + (buf ^ 1) * 32768;
#pragma unroll
            for (int jj = 0; jj < 4; jj++) {
                uint2 hi, lo;
                cvt_hilo(areg[jj], hi, lo);
                *(uint2*)(base + stoff[jj]) = hi;
                *(uint2*)(base + 8192 + stoff[jj]) = lo;
                *(uint4*)(base + 16384 + (jj * 256 + tid) * 16) = breg[jj];
            }
            __syncthreads();
        }
        buf ^= 1;
    }

    // epilogue: tanh + store
    size_t rbase = (size_t)blockIdx.y * 128 + wm;
    int cbase = blockIdx.x * 128 + wn;
#pragma unroll
    for (int i = 0; i < 4; i++) {
        size_t r0 = rbase + i * 16 + (lane >> 2);
#pragma unroll
        for (int j = 0; j < 4; j++) {
            int c0 = cbase + j * 8 + (lane & 3) * 2;
            float2 v0, v1;
            v0.x = tanhf(acc[i][j][0]); v0.y = tanhf(acc[i][j][1]);
            v1.x = tanhf(acc[i][j][2]); v1.y = tanhf(acc[i][j][3]);
            *(float2*)(g_patches + r0 * P_DIM + c0) = v0;
            *(float2*)(g_patches + (r0 + 8) * P_DIM + c0) = v1;
        }
    }
}

// ---------------- GEMM2 (mma.sync bf16 hi/lo): weighted col-sum of tanh(patches[sel] @ W_a1) ----------------
__global__ __launch_bounds__(256) void gemm2_mma_kernel() {
    int cnt = g_listcnt;
    int row0 = blockIdx.y * 128;
    if (row0 >= cnt) return;   // partials pre-zeroed
    extern __shared__ __align__(16) char sm[];
    __shared__ int sTok[128];
    __shared__ float sWt[128];
    __shared__ float sRed[8][32];
    const int tid = threadIdx.x, lane = tid & 31, wid = tid >> 5;
    const int wm = (wid & 1) << 6, wn = (wid >> 1) << 5;
    uint32_t sbase = smem_u32(sm);
    if (tid < 128) {
        int r = row0 + tid;
        if (r < cnt) {
            int ent = g_list[r];
            sTok[tid] = ent & 0xFFFFF;
            sWt[tid] = (float)(ent >> 20);
        } else {
            sTok[tid] = 0;
            sWt[tid] = 0.f;
        }
    }
    __syncthreads();

    const uint4* Bg = (const uint4*)g_Bsw2 + (size_t)blockIdx.x * 16 * 1024;
    const int srow = tid >> 1, kq = (tid & 1) << 4;
    const float* Arow = g_patches + (size_t)sTok[srow] * P_DIM;
    uint32_t stoff[4];
#pragma unroll
    for (int jj = 0; jj < 4; jj++) {
        int k0 = kq + jj * 4;
        stoff[jj] = srow * 64 + ((((k0 >> 3) ^ ((srow >> 1) & 3)) << 4)) + (k0 & 7) * 2;
    }

    float acc[4][4][4];
#pragma unroll
    for (int i = 0; i < 4; i++)
#pragma unroll
        for (int j = 0; j < 4; j++)
#pragma unroll
            for (int q = 0; q < 4; q++) acc[i][j][q] = 0.f;

    float4 areg[4];
    uint4 breg[4];
#pragma unroll
    for (int jj = 0; jj < 4; jj++) {
        areg[jj] = *(const float4*)(Arow + kq + jj * 4);
        breg[jj] = Bg[jj * 256 + tid];
    }
    {
        char* base = sm;
#pragma unroll
        for (int jj = 0; jj < 4; jj++) {
            uint2 hi, lo;
            cvt_hilo(areg[jj], hi, lo);
            *(uint2*)(base + stoff[jj]) = hi;
            *(uint2*)(base + 8192 + stoff[jj]) = lo;
            *(uint4*)(base + 16384 + (jj * 256 + tid) * 16) = breg[jj];
        }
    }
    __syncthreads();

    int buf = 0;
    for (int c = 0; c < 16; c++) {
        if (c < 15) {
#pragma unroll
            for (int jj = 0; jj < 4; jj++) {
                areg[jj] = *(const float4*)(Arow + (c + 1) * 32 + kq + jj * 4);
                breg[jj] = Bg[(c + 1) * 1024 + jj * 256 + tid];
            }
        }
        uint32_t Ah = sbase + buf * 32768;
        uint32_t Al = Ah + 8192;
        uint32_t Bh = Ah + 16384;
        uint32_t Bl = Ah + 24576;
        const int aw = lane & 7, aq = lane >> 3;
        const int bw = lane & 7, bq = (lane >> 3) & 1;
#pragma unroll
        for (int kk = 0; kk < 2; kk++) {
            uint32_t ahi[4][4], alo[4][4], bhi[4][2], blo[4][2];
            int ag = kk * 2 + (aq >> 1);
#pragma unroll
            for (int i = 0; i < 4; i++) {
                int r = wm + i * 16 + aw + ((aq & 1) << 3);
                uint32_t off = r * 64 + (((ag ^ ((r >> 1) & 3)) << 4));
                ldsm4(ahi[i], Ah + off);
                ldsm4(alo[i], Al + off);
            }
            int bg = kk * 2 + bq;
#pragma unroll
            for (int j = 0; j < 4; j++) {
                int n = wn + j * 8 + bw;
                uint32_t off = n * 64 + (((bg ^ ((n >> 1) & 3)) << 4));
                ldsm2(bhi[j], Bh + off);
                ldsm2(blo[j], Bl + off);
            }
#pragma unroll
            for (int i = 0; i < 4; i++)
#pragma unroll
                for (int j = 0; j < 4; j++) {
                    mma_bf16(acc[i][j], ahi[i], bhi[j]);
                    mma_bf16(acc[i][j], alo[i], bhi[j]);
                    mma_bf16(acc[i][j], ahi[i], blo[j]);
                }
        }
        if (c < 15) {
            char* base = sm + (buf ^ 1) * 32768;
#pragma unroll
            for (int jj = 0; jj < 4; jj++) {
                uint2 hi, lo;
                cvt_hilo(areg[jj], hi, lo);
                *(uint2*)(base + stoff[jj]) = hi;
                *(uint2*)(base + 8192 + stoff[jj]) = lo;
                *(uint4*)(base + 16384 + (jj * 256 + tid) * 16) = breg[jj];
            }
            __syncthreads();
        }
        buf ^= 1;
    }

    // epilogue: weighted sum of tanh over rows -> column partials
    float partial[8];
#pragma unroll
    for (int q = 0; q < 8; q++) partial[q] = 0.f;
#pragma unroll
    for (int i = 0; i < 4; i++) {
        float w0 = sWt[wm + i * 16 + (lane >> 2)];
        float w1 = sWt[wm + i * 16 + 8 + (lane >> 2)];
#pragma unroll
        for (int j = 0; j < 4; j++) {
            partial[j * 2 + 0] += w0 * tanhf(acc[i][j][0]) + w1 * tanhf(acc[i][j][2]);
            partial[j * 2 + 1] += w0 * tanhf(acc[i][j][1]) + w1 * tanhf(acc[i][j][3]);
        }
    }
#pragma unroll
    for (int o = 4; o < 32; o <<= 1)
#pragma unroll
        for (int q = 0; q < 8; q++)
            partial[q] += __shfl_xor_sync(0xffffffffu, partial[q], o);
    if (lane < 4) {
#pragma unroll
        for (int j = 0; j < 4; j++) {
            sRed[wid][j * 8 + (lane & 3) * 2 + 0] = partial[j * 2 + 0];
            sRed[wid][j * 8 + (lane & 3) * 2 + 1] = partial[j * 2 + 1];
        }
    }
    __syncthreads();
    if (tid < 128) {
        int c = tid;
        int w0 = (c >> 5) * 2;
        g_acc_part[blockIdx.y * 512 + blockIdx.x * 128 + c] =
            sRed[w0][c & 31] + sRed[w0 + 1][c & 31];
    }
}

// ---------------- router: logits for 3 gates, w_top0, masks ----------------
__global__ __launch_bounds__(256) void router_kernel(const float* __restrict__ Wg0,
                                                     const float* __restrict__ Wg1,
                                                     const float* __restrict__ Wg2,
                                                     float* __restrict__ out_rl) {
    __shared__ float sW[6][512];
    int tid = threadIdx.x;
    for (int p = tid; p < 512; p += 256) {
        sW[0][p] = Wg0[2 * p]; sW[1][p] = Wg0[2 * p + 1];
        sW[2][p] = Wg1[2 * p]; sW[3][p] = Wg1[2 * p + 1];
        sW[4][p] = Wg2[2 * p]; sW[5][p] = Wg2[2 * p + 1];
    }
    __syncthreads();
    int warp = tid >> 5, lane = tid & 31;
    int t = blockIdx.x * 8 + warp;
    const float* row = g_patches + (size_t)t * 512;
    float a0 = 0, b0 = 0, a1 = 0, b1 = 0, a2 = 0, b2 = 0;
    for (int k = lane; k < 512; k += 32) {
        float v = row[k];
        a0 += v * sW[0][k]; b0 += v * sW[1][k];
        a1 += v * sW[2][k]; b1 += v * sW[3][k];
        a2 += v * sW[4][k]; b2 += v * sW[5][k];
    }
#pragma unroll
    for (int o = 16; o; o >>= 1) {
        a0 += __shfl_xor_sync(0xffffffffu, a0, o);
        b0 += __shfl_xor_sync(0xffffffffu, b0, o);
        a1 += __shfl_xor_sync(0xffffffffu, a1, o);
        b1 += __shfl_xor_sync(0xffffffffu, b1, o);
        a2 += __shfl_xor_sync(0xffffffffu, a2, o);
        b2 += __shfl_xor_sync(0xffffffffu, b2, o);
    }
    if (lane == 0) {
        out_rl[2 * t] = a0;
        out_rl[2 * t + 1] = b0;
        float wt = 1.0f / (1.0f + expf(-fabsf(a0 - b0)));   // max of 2-way softmax
        g_wtop0[t] = wt;
        int mk = (b0 > a0 ? 1 : 0) | (b1 > a1 ? 2 : 0) | (b2 > a2 ? 4 : 0);
        g_mask[t] = (unsigned char)mk;
    }
}

// ---------------- radix threshold search over w_top0 bits ----------------
__global__ __launch_bounds__(256) void hist_kernel(int level) {
    __shared__ int sh[768];
    int nbins = (level == 2) ? 128 : 256;
    int shift = (level == 0) ? 15 : (level == 1) ? 7 : 0;
    int hs = (level == 0) ? 23 : (level == 1) ? 15 : 7;
    int* hist = (level == 0) ? g_histA : (level == 1) ? g_histB : g_histC;
    int tid = threadIdx.x;
    int nb3 = 3 * nbins;
    for (int i = tid; i < nb3; i += 256) sh[i] = 0;
    __syncthreads();
    unsigned p0 = g_pre[0] >> hs, p1 = g_pre[1] >> hs, p2 = g_pre[2] >> hs;
    int stride = gridDim.x * 256;
    for (int t = blockIdx.x * 256 + tid; t < T_TOK; t += stride) {
        unsigned u = __float_as_uint(g_wtop0[t]);
        unsigned v = u - 0x3F000000u;
        if (v > 0x7FFFFFu) v = 0x7FFFFFu;
        int mk = g_mask[t];
        unsigned vh = v >> hs;
        int bin = (int)((v >> shift) & (unsigned)(nbins - 1));
        if ((mk & 1) && vh == p0) atomicAdd(&sh[bin], 1);
        if ((mk & 2) && vh == p1) atomicAdd(&sh[nbins + bin], 1);
        if ((mk & 4) && vh == p2) atomicAdd(&sh[2 * nbins + bin], 1);
    }
    __syncthreads();
    for (int i = tid; i < nb3; i += 256)
        if (sh[i]) atomicAdd(&hist[i], sh[i]);
}

__global__ void find_kernel(int level) {
    __shared__ int sh[768];
    int nbins = (level == 2) ? 128 : 256;
    int shift = (level == 0) ? 15 : (level == 1) ? 7 : 0;
    const int* hist = (level == 0) ? g_histA : (level == 1) ? g_histB : g_histC;
    int tid = threadIdx.x;
    for (int i = tid; i < 3 * nbins; i += blockDim.x) sh[i] = hist[i];
    __syncthreads();
    if (tid < 3) {
        int e = tid;
        unsigned prefix;
        int rem;
        if (level == 0) {
            int tot = 0;
            for (int b = 0; b < nbins; b++) tot += sh[e * nbins + b];
            const float fr = (e == 1) ? 0.5f : 0.25f;
            int nums = (int)floorf((float)tot * fr);
            if (nums == 0) nums = tot;
            g_cnt[e] = tot;
            g_nums[e] = nums;
            prefix = 0u;
            rem = nums;
        } else {
            prefix = g_pre[e];
            rem = g_rem[e];
        }
        int acc = 0;
        int b;
        for (b = nbins - 1; b >= 0; b--) {
            int c = sh[e * nbins + b];
            if (acc + c >= rem) break;
            acc += c;
        }
        if (b < 0) b = 0;
        rem -= acc;
        prefix |= ((unsigned)b) << shift;
        g_pre[e] = prefix;
        g_rem[e] = rem;
    }
}

// ---------------- ordered selection + stable tie-break + deterministic compaction ----------------
__global__ __launch_bounds__(1024) void select_kernel() {
    __shared__ int warpcnt[32][4];
    int tid = threadIdx.x, wid = tid >> 5, lane = tid & 31;
    unsigned pre[3];
    int tt[3];
#pragma unroll
    for (int e = 0; e < 3; e++) { pre[e] = g_pre[e]; tt[e] = g_rem[e]; }
    int base[4] = {0, 0, 0, 0};
    for (int start = 0; start < T_TOK; start += 1024) {
        int t = start + tid;
        unsigned v = __float_as_uint(g_wtop0[t]) - 0x3F000000u;
        if (v > 0x7FFFFFu) v = 0x7FFFFFu;
        int mk = g_mask[t];
        int r[3];
        bool gt[3], eq[3];
#pragma unroll
        for (int e = 0; e < 3; e++) {
            bool m = ((mk >> e) & 1) != 0;
            eq[e] = m && (v == pre[e]);
            gt[e] = m && (v > pre[e]);
            unsigned bal = __ballot_sync(0xffffffffu, eq[e]);
            r[e] = __popc(bal & ((1u << lane) - 1u));
            if (lane == 0) warpcnt[wid][e] = __popc(bal);
        }
        __syncthreads();
        int wb[3] = {0, 0, 0}, ct[3] = {0, 0, 0};
        for (int w = 0; w < 32; w++) {
#pragma unroll
            for (int e = 0; e < 3; e++) {
                int c = warpcnt[w][e];
                if (w < wid) wb[e] += c;
                ct[e] += c;
            }
        }
        int selbits = 0;
#pragma unroll
        for (int e = 0; e < 3; e++) {
            int rank = base[e] + wb[e] + r[e];
            if (gt[e] || (eq[e] && rank < tt[e])) selbits |= 1 << e;
        }
        g_w[t] = (unsigned char)selbits;
        int wmul = __popc((unsigned)selbits);
        bool has = wmul > 0;
        unsigned bal3 = __ballot_sync(0xffffffffu, has);
        int r3 = __popc(bal3 & ((1u << lane) - 1u));
        if (lane == 0) warpcnt[wid][3] = __popc(bal3);
        __syncthreads();
        int wb3 = 0, ct3 = 0;
        for (int w = 0; w < 32; w++) {
            int c = warpcnt[w][3];
            if (w < wid) wb3 += c;
            ct3 += c;
        }
        if (has) g_list[base[3] + wb3 + r3] = t | (wmul << 20);
        base[0] += ct[0]; base[1] += ct[1]; base[2] += ct[2]; base[3] += ct3;
        __syncthreads();
    }
    if (tid == 0) g_listcnt = base[3];
}

// ---------------- weighted column sums of patches (bag + 3 expert sums), deterministic ----------------
__global__ __launch_bounds__(512) void msum_kernel() {
    int blk = blockIdx.x;          // 128 blocks
    int p = threadIdx.x;           // 512 columns
    int t0 = blk * 512;
    float sb = 0.f, s0 = 0.f, s1 = 0.f, s2 = 0.f;
    for (int i = 0; i < 512; i++) {
        int t = t0 + i;
        float v = g_patches[(size_t)t * 512 + p];
        sb += v;
        int w = g_w[t];
        if (w & 1) s0 += v;
        if (w & 2) s1 += v;
        if (w & 4) s2 += v;
    }
    float* base = &g_ms_part[blk * 4 * 512];
    base[p] = sb;
    base[512 + p] = s0;
    base[1024 + p] = s1;
    base[1536 + p] = s2;
}

__global__ __launch_bounds__(512) void msum_reduce_kernel() {
    int p = threadIdx.x;
    float sb = 0.f, s0 = 0.f, s1 = 0.f, s2 = 0.f;
    for (int b = 0; b < 128; b++) {
        const float* base = &g_ms_part[b * 4 * 512];
        sb += base[p];
        s0 += base[512 + p];
        s1 += base[1024 + p];
        s2 += base[1536 + p];
    }
    g_bag[p] = sb;
    g_ms[0][p] = s0;
    g_ms[1][p] = s1;
    g_ms[2][p] = s2;
}

// ---------------- block reduction helper (512 threads) ----------------
__device__ float blockReduce512(float v, float* red) {
    int tid = threadIdx.x;
    red[tid] = v;
    __syncthreads();
    for (int s = 256; s > 0; s >>= 1) {
        if (tid < s) red[tid] += red[tid + s];
        __syncthreads();
    }
    float r = red[0];
    __syncthreads();
    return r;
}

// ---------------- trans1 outputs + expert CE losses + distribute ----------------
__global__ __launch_bounds__(512) void finalize1_kernel(const float* __restrict__ W_cls1,
                                                        const float* __restrict__ W_clf,
                                                        float* __restrict__ out) {
    __shared__ float red[512];
    int p = threadIdx.x;
    float bagmean = g_bag[p] * (1.0f / 65536.0f);
    float yl0 = blockReduce512(bagmean * W_cls1[2 * p], red);
    float yl1 = blockReduce512(bagmean * W_cls1[2 * p + 1], red);
    float l[3][3];
    for (int e = 0; e < 3; e++) {
        int nd = g_nums[e];
        if (nd < 1) nd = 1;
        float mf = g_ms[e][p] / (float)nd;
        for (int c = 0; c < 3; c++)
            l[e][c] = blockReduce512(mf * W_clf[(e * 512 + p) * 3 + c], red);
    }
    if (p == 0) {
        out[3] = yl0;
        out[4] = yl1;
        float m = fmaxf(yl0, yl1);
        float e0 = expf(yl0 - m), e1 = expf(yl1 - m);
        float s = e0 + e1;
        out[5] = e0 / s;
        out[6] = e1 / s;
        out[7] = (yl1 > yl0) ? 1.f : 0.f;
        float loss = 0.f;
        for (int e = 0; e < 2; e++) {
            float m3 = fmaxf(l[e][0], fmaxf(l[e][1], l[e][2]));
            float lse = logf(expf(l[e][0] - m3) + expf(l[e][1] - m3) + expf(l[e][2] - m3));
            loss += -(l[e][e] - m3 - lse);
        }
        out[131080] = loss;
        out[131081] = 65536.f;
        out[131082] = (float)g_nums[0];
        out[131083] = (float)g_nums[1];
        out[131084] = (float)g_nums[2];
    }
}

__global__ __launch_bounds__(512) void acc_reduce_kernel() {
    int p = threadIdx.x;
    float s = 0.f;
    for (int rt = 0; rt < 512; rt++) s += g_acc_part[rt * 512 + p];
    g_acc[p] = s;
}

// ---------------- aggregated classifier outputs ----------------
__global__ __launch_bounds__(512) void finalize2_kernel(const float* __restrict__ W_acls,
                                                        float* __restrict__ out) {
    __shared__ float red[512];
    int p = threadIdx.x;
    float tn = (float)(g_nums[0] + g_nums[1] + g_nums[2]);
    float d = fmaxf(tn, 1.0f);
    float a = g_acc[p] / d;
    float el0 = blockReduce512(a * W_acls[2 * p], red);
    float el1 = blockReduce512(a * W_acls[2 * p + 1], red);
    if (p == 0) {
        out[0] = el0;
        out[1] = el1;
        out[2] = (el1 > el0) ? 1.f : 0.f;
    }
}

// ---------------- launch ----------------
extern "C" void kernel_launch(void* const* d_in, const int* in_sizes, int n_in,
                              void* d_out, int out_size) {
    (void)in_sizes; (void)n_in; (void)out_size;
    const float* hidden = (const float*)d_in[0];
    const float* W_t1   = (const float*)d_in[1];
    const float* W_cls1 = (const float*)d_in[2];
    const float* Wg0    = (const float*)d_in[3];
    const float* Wg1    = (const float*)d_in[4];
    const float* Wg2    = (const float*)d_in[5];
    const float* W_clf  = (const float*)d_in[6];
    const float* W_a1   = (const float*)d_in[7];
    const float* W_acls = (const float*)d_in[8];
    float* out = (float*)d_out;

    static int s_attr_done = 0;
    cudaFuncSetAttribute(gemm1_mma_kernel, cudaFuncAttributeMaxDynamicSharedMemorySize, 65536);
    cudaFuncSetAttribute(gemm2_mma_kernel, cudaFuncAttributeMaxDynamicSharedMemorySize, 65536);
    (void)s_attr_done;

    zero_kernel<<<512, 256>>>();
    prep_kernel<<<4096, 256>>>(W_t1, 32, 0);
    prep_kernel<<<2048, 256>>>(W_a1, 16, 1);

    dim3 g1(4, 512);
    gemm1_mma_kernel<<<g1, 256, 65536>>>(hidden);

    router_kernel<<<8192, 256>>>(Wg0, Wg1, Wg2, out + 8);

    hist_kernel<<<64, 256>>>(0);
    find_kernel<<<1, 256>>>(0);
    hist_kernel<<<64, 256>>>(1);
    find_kernel<<<1, 256>>>(1);
    hist_kernel<<<64, 256>>>(2);
    find_kernel<<<1, 256>>>(2);

    select_kernel<<<1, 1024>>>();

    msum_kernel<<<128, 512>>>();
    msum_reduce_kernel<<<1, 512>>>();
    finalize1_kernel<<<1, 512>>>(W_cls1, W_clf, out);

    dim3 g2(4, 512);
    gemm2_mma_kernel<<<g2, 256, 65536>>>();
    acc_reduce_kernel<<<1, 512>>>();
    finalize2_kernel<<<1, 512>>>(W_acls, out);
}

// round 14
// speedup vs baseline: 2.2846x; 1.1578x over previous
#include <cuda_runtime.h>
#include <cuda_bf16.h>
#include <math.h>
#include <stdint.h>

#define T_TOK 65536
#define P_DIM 512
#define D_DIM 1024

// ---------------- scratch (device globals; no allocation allowed) ----------------
__device__ float g_patches[(size_t)T_TOK * P_DIM];   // 134 MB
__device__ __align__(16) uint4 g_A1[512 * 32 * 1024];            // 256 MB: A bf16 hi/lo swizzled tiles
__device__ __align__(16) unsigned char g_Bsw1[2 * 1024 * 1024];  // gemm1 B: 4bx x 32ch x {hi,lo} x 8KB
__device__ __align__(16) unsigned char g_Bsw2[1024 * 1024];      // gemm2 B: 4bx x 16ch x {hi,lo} x 8KB
__device__ float g_wtop0[T_TOK];
__device__ unsigned char g_mask[T_TOK];
__device__ unsigned char g_w[T_TOK];
__device__ int g_list[T_TOK];
__device__ int g_listcnt;
__device__ int g_histA[768];      // level0: 3 x 256
__device__ int g_histB[768];      // level1: 3 x 256
__device__ int g_histC[384];      // level2: 3 x 128
__device__ unsigned g_pre[3];
__device__ int g_rem[3];
__device__ int g_nums[3];
__device__ int g_cnt[3];
__device__ float g_ms_part[128 * 4 * 512];  // per-block partials: [blk][bag,e0,e1,e2][p]
__device__ float g_bag[512];
__device__ float g_ms[3][512];
__device__ float g_acc_part[512 * 512];     // gemm2 partials: [rowtile][p]
__device__ float g_acc[512];

// ---------------- PTX helpers: ldmatrix + bf16 mma + cp.async (legal on compute_103) ----------------
__device__ __forceinline__ uint32_t smem_u32(const void* p) {
    uint32_t a;
    asm("{ .reg .u64 t; cvta.to.shared.u64 t, %1; cvt.u32.u64 %0, t; }" : "=r"(a) : "l"(p));
    return a;
}
__device__ __forceinline__ void ldsm4(uint32_t* r, uint32_t addr) {
    asm volatile("ldmatrix.sync.aligned.m8n8.x4.shared.b16 {%0,%1,%2,%3}, [%4];"
                 : "=r"(r[0]), "=r"(r[1]), "=r"(r[2]), "=r"(r[3]) : "r"(addr));
}
__device__ __forceinline__ void ldsm2(uint32_t* r, uint32_t addr) {
    asm volatile("ldmatrix.sync.aligned.m8n8.x2.shared.b16 {%0,%1}, [%2];"
                 : "=r"(r[0]), "=r"(r[1]) : "r"(addr));
}
__device__ __forceinline__ void mma_bf16(float* c, const uint32_t* a, const uint32_t* b) {
    asm volatile("mma.sync.aligned.m16n8k16.row.col.f32.bf16.bf16.f32 "
                 "{%0,%1,%2,%3}, {%4,%5,%6,%7}, {%8,%9}, {%0,%1,%2,%3};"
                 : "+f"(c[0]), "+f"(c[1]), "+f"(c[2]), "+f"(c[3])
                 : "r"(a[0]), "r"(a[1]), "r"(a[2]), "r"(a[3]), "r"(b[0]), "r"(b[1]));
}
__device__ __forceinline__ void cp16(uint32_t saddr, const void* gptr) {
    asm volatile("cp.async.cg.shared.global [%0], [%1], 16;" :: "r"(saddr), "l"(gptr));
}
__device__ __forceinline__ void cp_commit() { asm volatile("cp.async.commit_group;"); }
__device__ __forceinline__ void cvt_hilo(float4 v, uint2& hi, uint2& lo) {
    __nv_bfloat16 hx = __float2bfloat16(v.x), hy = __float2bfloat16(v.y);
    __nv_bfloat16 hz = __float2bfloat16(v.z), hw = __float2bfloat16(v.w);
    __nv_bfloat16 lx = __float2bfloat16(v.x - __bfloat162float(hx));
    __nv_bfloat16 ly = __float2bfloat16(v.y - __bfloat162float(hy));
    __nv_bfloat16 lz = __float2bfloat16(v.z - __bfloat162float(hz));
    __nv_bfloat16 lw = __float2bfloat16(v.w - __bfloat162float(hw));
    __nv_bfloat162 h01, h23, l01, l23;
    h01.x = hx; h01.y = hy; h23.x = hz; h23.y = hw;
    l01.x = lx; l01.y = ly; l23.x = lz; l23.y = lw;
    hi.x = *(uint32_t*)&h01; hi.y = *(uint32_t*)&h23;
    lo.x = *(uint32_t*)&l01; lo.y = *(uint32_t*)&l23;
}

// ---------------- zero accumulators (every launch; graph-replay safe) ----------------
__global__ void zero_kernel() {
    int i = blockIdx.x * blockDim.x + threadIdx.x;
    int stride = gridDim.x * blockDim.x;
    for (int idx = i; idx < 512 * 512; idx += stride) g_acc_part[idx] = 0.f;
    if (i < 768) { g_histA[i] = 0; g_histB[i] = 0; }
    if (i < 384) g_histC[i] = 0;
    if (i < 3) g_pre[i] = 0u;
}

// ---------------- A prep: hidden (65536x1024 fp32) -> swizzled bf16 hi/lo tiles ----------------
// tile layout per (rowtile, chunk): 16KB = hi 8KB + lo 8KB; byte(hi) = r*64 + ((kg ^ ((r>>1)&3))<<4) + (k&7)*2
__global__ __launch_bounds__(256) void prepA_kernel(const float* __restrict__ A) {
    int idx = blockIdx.x * 256 + threadIdx.x;   // 32768 blocks -> 8388608 threads
    int kg = idx & 3;
    int r = (idx >> 2) & 127;
    int chunk = (idx >> 9) & 31;
    int rt = idx >> 14;
    const float* src = A + (size_t)(rt * 128 + r) * 1024 + chunk * 32 + kg * 8;
    float4 v0 = *(const float4*)(src);
    float4 v1 = *(const float4*)(src + 4);
    uint2 h0, l0, h1, l1;
    cvt_hilo(v0, h0, l0);
    cvt_hilo(v1, h1, l1);
    uint4 hi = make_uint4(h0.x, h0.y, h1.x, h1.y);
    uint4 lo = make_uint4(l0.x, l0.y, l1.x, l1.y);
    size_t tilebase = (size_t)(rt * 32 + chunk) * 1024;   // uint4 units
    int off16 = r * 4 + (kg ^ ((r >> 1) & 3));
    g_A1[tilebase + off16] = hi;
    g_A1[tilebase + 512 + off16] = lo;
}

// ---------------- B prep: W (K x 512) -> pre-swizzled bf16 hi/lo tiles in global ----------------
__global__ __launch_bounds__(256) void prep_kernel(const float* __restrict__ W, int nchunk, int which) {
    unsigned char* dst = which ? g_Bsw2 : g_Bsw1;
    int idx = blockIdx.x * 256 + threadIdx.x;
    int total = 4 * nchunk * 2 * 128 * 32;
    if (idx >= total) return;
    int k = idx & 31;
    int n = (idx >> 5) & 127;
    int h = (idx >> 12) & 1;
    int rest = idx >> 13;
    int chunk = rest % nchunk;
    int bx = rest / nchunk;
    float w = W[(size_t)(chunk * 32 + k) * 512 + bx * 128 + n];
    __nv_bfloat16 hi = __float2bfloat16(w);
    __nv_bfloat16 v = h ? __float2bfloat16(w - __bfloat162float(hi)) : hi;
    size_t tile = (size_t)(bx * nchunk + chunk) * 2 + h;
    size_t off = tile * 8192 + n * 64 + ((((k >> 3) ^ ((n >> 1) & 3)) << 4)) + (k & 7) * 2;
    *(__nv_bfloat16*)(dst + off) = v;
}

// ---------------- GEMM1 (mma.sync bf16 hi/lo, cp.async): patches = tanh(X @ W_t1) ----------------
// smem per buffer (32KB): Ahi@0, Alo@8192, Bhi@16384, Blo@24576; double buffered = 64KB.
__global__ __launch_bounds__(256, 2) void gemm1_mma_kernel() {
    extern __shared__ __align__(16) char sm[];
    const int tid = threadIdx.x, lane = tid & 31, wid = tid >> 5;
    const int wm = (wid & 1) << 6, wn = (wid >> 1) << 5;
    uint32_t sbase = smem_u32(sm);
    const uint4* Ag = g_A1 + (size_t)blockIdx.y * 32 * 1024;
    const uint4* Bg = (const uint4*)g_Bsw1 + (size_t)blockIdx.x * 32 * 1024;

    float acc[4][4][4];
#pragma unroll
    for (int i = 0; i < 4; i++)
#pragma unroll
        for (int j = 0; j < 4; j++)
#pragma unroll
            for (int q = 0; q < 4; q++) acc[i][j][q] = 0.f;

    // prologue: chunk 0 into buf 0
    {
        uint32_t sb = sbase;
        const uint4* As = Ag;
        const uint4* Bs = Bg;
#pragma unroll
        for (int j = 0; j < 4; j++) {
            cp16(sb + (tid + j * 256) * 16, As + tid + j * 256);
            cp16(sb + 16384 + (tid + j * 256) * 16, Bs + tid + j * 256);
        }
        cp_commit();
    }

    int buf = 0;
    for (int c = 0; c < 32; c++) {
        if (c < 31) {
            uint32_t sb = sbase + (buf ^ 1) * 32768;
            const uint4* As = Ag + (c + 1) * 1024;
            const uint4* Bs = Bg + (c + 1) * 1024;
#pragma unroll
            for (int j = 0; j < 4; j++) {
                cp16(sb + (tid + j * 256) * 16, As + tid + j * 256);
                cp16(sb + 16384 + (tid + j * 256) * 16, Bs + tid + j * 256);
            }
            cp_commit();
            asm volatile("cp.async.wait_group 1;");
        } else {
            asm volatile("cp.async.wait_group 0;");
        }
        __syncthreads();

        uint32_t Ah = sbase + buf * 32768;
        uint32_t Al = Ah + 8192;
        uint32_t Bh = Ah + 16384;
        uint32_t Bl = Ah + 24576;
        const int g = lane >> 3, w8 = lane & 7;
#pragma unroll
        for (int kk = 0; kk < 2; kk++) {
            uint32_t bhi[2][4], blo[2][4];
#pragma unroll
            for (int jj = 0; jj < 2; jj++) {
                int n = wn + jj * 16 + ((g >> 1) << 3) + w8;
                int kgrp = kk * 2 + (g & 1);
                uint32_t off = n * 64 + (((kgrp ^ ((n >> 1) & 3)) << 4));
                ldsm4(bhi[jj], Bh + off);
                ldsm4(blo[jj], Bl + off);
            }
#pragma unroll
            for (int i = 0; i < 4; i++) {
                uint32_t ahi[4], alo[4];
                int r = wm + i * 16 + w8 + ((g & 1) << 3);
                int ag = kk * 2 + (g >> 1);
                uint32_t off = r * 64 + (((ag ^ ((r >> 1) & 3)) << 4));
                ldsm4(ahi, Ah + off);
                ldsm4(alo, Al + off);
#pragma unroll
                for (int j = 0; j < 4; j++) {
                    const uint32_t* bh = &bhi[j >> 1][(j & 1) * 2];
                    const uint32_t* bl = &blo[j >> 1][(j & 1) * 2];
                    mma_bf16(acc[i][j], ahi, bh);
                    mma_bf16(acc[i][j], alo, bh);
                    mma_bf16(acc[i][j], ahi, bl);
                }
            }
        }
        __syncthreads();
        buf ^= 1;
    }

    // epilogue: tanh + store
    size_t rbase = (size_t)blockIdx.y * 128 + wm;
    int cbase = blockIdx.x * 128 + wn;
#pragma unroll
    for (int i = 0; i < 4; i++) {
        size_t r0 = rbase + i * 16 + (lane >> 2);
#pragma unroll
        for (int j = 0; j < 4; j++) {
            int c0 = cbase + j * 8 + (lane & 3) * 2;
            float2 v0, v1;
            v0.x = tanhf(acc[i][j][0]); v0.y = tanhf(acc[i][j][1]);
            v1.x = tanhf(acc[i][j][2]); v1.y = tanhf(acc[i][j][3]);
            *(float2*)(g_patches + r0 * P_DIM + c0) = v0;
            *(float2*)(g_patches + (r0 + 8) * P_DIM + c0) = v1;
        }
    }
}

// ---------------- GEMM2 (mma.sync bf16 hi/lo): weighted col-sum of tanh(patches[sel] @ W_a1) ----------------
__global__ __launch_bounds__(256) void gemm2_mma_kernel() {
    int cnt = g_listcnt;
    int row0 = blockIdx.y * 128;
    if (row0 >= cnt) return;   // partials pre-zeroed
    extern __shared__ __align__(16) char sm[];
    __shared__ int sTok[128];
    __shared__ float sWt[128];
    __shared__ float sRed[8][32];
    const int tid = threadIdx.x, lane = tid & 31, wid = tid >> 5;
    const int wm = (wid & 1) << 6, wn = (wid >> 1) << 5;
    uint32_t sbase = smem_u32(sm);
    if (tid < 128) {
        int r = row0 + tid;
        if (r < cnt) {
            int ent = g_list[r];
            sTok[tid] = ent & 0xFFFFF;
            sWt[tid] = (float)(ent >> 20);
        } else {
            sTok[tid] = 0;
            sWt[tid] = 0.f;
        }
    }
    __syncthreads();

    const uint4* Bg = (const uint4*)g_Bsw2 + (size_t)blockIdx.x * 16 * 1024;
    const int srow = tid >> 1, kq = (tid & 1) << 4;
    const float* Arow = g_patches + (size_t)sTok[srow] * P_DIM;
    uint32_t stoff[4];
#pragma unroll
    for (int jj = 0; jj < 4; jj++) {
        int k0 = kq + jj * 4;
        stoff[jj] = srow * 64 + ((((k0 >> 3) ^ ((srow >> 1) & 3)) << 4)) + (k0 & 7) * 2;
    }

    float acc[4][4][4];
#pragma unroll
    for (int i = 0; i < 4; i++)
#pragma unroll
        for (int j = 0; j < 4; j++)
#pragma unroll
            for (int q = 0; q < 4; q++) acc[i][j][q] = 0.f;

    float4 areg[4];
    uint4 breg[4];
#pragma unroll
    for (int jj = 0; jj < 4; jj++) {
        areg[jj] = *(const float4*)(Arow + kq + jj * 4);
        breg[jj] = Bg[jj * 256 + tid];
    }
    {
        char* base = sm;
#pragma unroll
        for (int jj = 0; jj < 4; jj++) {
            uint2 hi, lo;
            cvt_hilo(areg[jj], hi, lo);
            *(uint2*)(base + stoff[jj]) = hi;
            *(uint2*)(base + 8192 + stoff[jj]) = lo;
            *(uint4*)(base + 16384 + (jj * 256 + tid) * 16) = breg[jj];
        }
    }
    __syncthreads();

    int buf = 0;
    for (int c = 0; c < 16; c++) {
        if (c < 15) {
#pragma unroll
            for (int jj = 0; jj < 4; jj++) {
                areg[jj] = *(const float4*)(Arow + (c + 1) * 32 + kq + jj * 4);
                breg[jj] = Bg[(c + 1) * 1024 + jj * 256 + tid];
            }
        }
        uint32_t Ah = sbase + buf * 32768;
        uint32_t Al = Ah + 8192;
        uint32_t Bh = Ah + 16384;
        uint32_t Bl = Ah + 24576;
        const int aw = lane & 7, aq = lane >> 3;
        const int bw = lane & 7, bq = (lane >> 3) & 1;
#pragma unroll
        for (int kk = 0; kk < 2; kk++) {
            uint32_t ahi[4][4], alo[4][4], bhi[4][2], blo[4][2];
            int ag = kk * 2 + (aq >> 1);
#pragma unroll
            for (int i = 0; i < 4; i++) {
                int r = wm + i * 16 + aw + ((aq & 1) << 3);
                uint32_t off = r * 64 + (((ag ^ ((r >> 1) & 3)) << 4));
                ldsm4(ahi[i], Ah + off);
                ldsm4(alo[i], Al + off);
            }
            int bg = kk * 2 + bq;
#pragma unroll
            for (int j = 0; j < 4; j++) {
                int n = wn + j * 8 + bw;
                uint32_t off = n * 64 + (((bg ^ ((n >> 1) & 3)) << 4));
                ldsm2(bhi[j], Bh + off);
                ldsm2(blo[j], Bl + off);
            }
#pragma unroll
            for (int i = 0; i < 4; i++)
#pragma unroll
                for (int j = 0; j < 4; j++) {
                    mma_bf16(acc[i][j], ahi[i], bhi[j]);
                    mma_bf16(acc[i][j], alo[i], bhi[j]);
                    mma_bf16(acc[i][j], ahi[i], blo[j]);
                }
        }
        if (c < 15) {
            char* base = sm + (buf ^ 1) * 32768;
#pragma unroll
            for (int jj = 0; jj < 4; jj++) {
                uint2 hi, lo;
                cvt_hilo(areg[jj], hi, lo);
                *(uint2*)(base + stoff[jj]) = hi;
                *(uint2*)(base + 8192 + stoff[jj]) = lo;
                *(uint4*)(base + 16384 + (jj * 256 + tid) * 16) = breg[jj];
            }
            __syncthreads();
        }
        buf ^= 1;
    }

    // epilogue: weighted sum of tanh over rows -> column partials
    float partial[8];
#pragma unroll
    for (int q = 0; q < 8; q++) partial[q] = 0.f;
#pragma unroll
    for (int i = 0; i < 4; i++) {
        float w0 = sWt[wm + i * 16 + (lane >> 2)];
        float w1 = sWt[wm + i * 16 + 8 + (lane >> 2)];
#pragma unroll
        for (int j = 0; j < 4; j++) {
            partial[j * 2 + 0] += w0 * tanhf(acc[i][j][0]) + w1 * tanhf(acc[i][j][2]);
            partial[j * 2 + 1] += w0 * tanhf(acc[i][j][1]) + w1 * tanhf(acc[i][j][3]);
        }
    }
#pragma unroll
    for (int o = 4; o < 32; o <<= 1)
#pragma unroll
        for (int q = 0; q < 8; q++)
            partial[q] += __shfl_xor_sync(0xffffffffu, partial[q], o);
    if (lane < 4) {
#pragma unroll
        for (int j = 0; j < 4; j++) {
            sRed[wid][j * 8 + (lane & 3) * 2 + 0] = partial[j * 2 + 0];
            sRed[wid][j * 8 + (lane & 3) * 2 + 1] = partial[j * 2 + 1];
        }
    }
    __syncthreads();
    if (tid < 128) {
        int c = tid;
        int w0 = (c >> 5) * 2;
        g_acc_part[blockIdx.y * 512 + blockIdx.x * 128 + c] =
            sRed[w0][c & 31] + sRed[w0 + 1][c & 31];
    }
}

// ---------------- router: logits for 3 gates, w_top0, masks ----------------
__global__ __launch_bounds__(256) void router_kernel(const float* __restrict__ Wg0,
                                                     const float* __restrict__ Wg1,
                                                     const float* __restrict__ Wg2,
                                                     float* __restrict__ out_rl) {
    __shared__ float sW[6][512];
    int tid = threadIdx.x;
    for (int p = tid; p < 512; p += 256) {
        sW[0][p] = Wg0[2 * p]; sW[1][p] = Wg0[2 * p + 1];
        sW[2][p] = Wg1[2 * p]; sW[3][p] = Wg1[2 * p + 1];
        sW[4][p] = Wg2[2 * p]; sW[5][p] = Wg2[2 * p + 1];
    }
    __syncthreads();
    int warp = tid >> 5, lane = tid & 31;
    int t = blockIdx.x * 8 + warp;
    const float* row = g_patches + (size_t)t * 512;
    float a0 = 0, b0 = 0, a1 = 0, b1 = 0, a2 = 0, b2 = 0;
    for (int k = lane; k < 512; k += 32) {
        float v = row[k];
        a0 += v * sW[0][k]; b0 += v * sW[1][k];
        a1 += v * sW[2][k]; b1 += v * sW[3][k];
        a2 += v * sW[4][k]; b2 += v * sW[5][k];
    }
#pragma unroll
    for (int o = 16; o; o >>= 1) {
        a0 += __shfl_xor_sync(0xffffffffu, a0, o);
        b0 += __shfl_xor_sync(0xffffffffu, b0, o);
        a1 += __shfl_xor_sync(0xffffffffu, a1, o);
        b1 += __shfl_xor_sync(0xffffffffu, b1, o);
        a2 += __shfl_xor_sync(0xffffffffu, a2, o);
        b2 += __shfl_xor_sync(0xffffffffu, b2, o);
    }
    if (lane == 0) {
        out_rl[2 * t] = a0;
        out_rl[2 * t + 1] = b0;
        float wt = 1.0f / (1.0f + expf(-fabsf(a0 - b0)));   // max of 2-way softmax
        g_wtop0[t] = wt;
        int mk = (b0 > a0 ? 1 : 0) | (b1 > a1 ? 2 : 0) | (b2 > a2 ? 4 : 0);
        g_mask[t] = (unsigned char)mk;
    }
}

// ---------------- radix threshold search over w_top0 bits ----------------
__global__ __launch_bounds__(256) void hist_kernel(int level) {
    __shared__ int sh[768];
    int nbins = (level == 2) ? 128 : 256;
    int shift = (level == 0) ? 15 : (level == 1) ? 7 : 0;
    int hs = (level == 0) ? 23 : (level == 1) ? 15 : 7;
    int* hist = (level == 0) ? g_histA : (level == 1) ? g_histB : g_histC;
    int tid = threadIdx.x;
    int nb3 = 3 * nbins;
    for (int i = tid; i < nb3; i += 256) sh[i] = 0;
    __syncthreads();
    unsigned p0 = g_pre[0] >> hs, p1 = g_pre[1] >> hs, p2 = g_pre[2] >> hs;
    int stride = gridDim.x * 256;
    for (int t = blockIdx.x * 256 + tid; t < T_TOK; t += stride) {
        unsigned u = __float_as_uint(g_wtop0[t]);
        unsigned v = u - 0x3F000000u;
        if (v > 0x7FFFFFu) v = 0x7FFFFFu;
        int mk = g_mask[t];
        unsigned vh = v >> hs;
        int bin = (int)((v >> shift) & (unsigned)(nbins - 1));
        if ((mk & 1) && vh == p0) atomicAdd(&sh[bin], 1);
        if ((mk & 2) && vh == p1) atomicAdd(&sh[nbins + bin], 1);
        if ((mk & 4) && vh == p2) atomicAdd(&sh[2 * nbins + bin], 1);
    }
    __syncthreads();
    for (int i = tid; i < nb3; i += 256)
        if (sh[i]) atomicAdd(&hist[i], sh[i]);
}

__global__ void find_kernel(int level) {
    __shared__ int sh[768];
    int nbins = (level == 2) ? 128 : 256;
    int shift = (level == 0) ? 15 : (level == 1) ? 7 : 0;
    const int* hist = (level == 0) ? g_histA : (level == 1) ? g_histB : g_histC;
    int tid = threadIdx.x;
    for (int i = tid; i < 3 * nbins; i += blockDim.x) sh[i] = hist[i];
    __syncthreads();
    if (tid < 3) {
        int e = tid;
        unsigned prefix;
        int rem;
        if (level == 0) {
            int tot = 0;
            for (int b = 0; b < nbins; b++) tot += sh[e * nbins + b];
            const float fr = (e == 1) ? 0.5f : 0.25f;
            int nums = (int)floorf((float)tot * fr);
            if (nums == 0) nums = tot;
            g_cnt[e] = tot;
            g_nums[e] = nums;
            prefix = 0u;
            rem = nums;
        } else {
            prefix = g_pre[e];
            rem = g_rem[e];
        }
        int acc = 0;
        int b;
        for (b = nbins - 1; b >= 0; b--) {
            int c = sh[e * nbins + b];
            if (acc + c >= rem) break;
            acc += c;
        }
        if (b < 0) b = 0;
        rem -= acc;
        prefix |= ((unsigned)b) << shift;
        g_pre[e] = prefix;
        g_rem[e] = rem;
    }
}

// ---------------- ordered selection + stable tie-break + deterministic compaction ----------------
__global__ __launch_bounds__(1024) void select_kernel() {
    __shared__ int warpcnt[32][4];
    int tid = threadIdx.x, wid = tid >> 5, lane = tid & 31;
    unsigned pre[3];
    int tt[3];
#pragma unroll
    for (int e = 0; e < 3; e++) { pre[e] = g_pre[e]; tt[e] = g_rem[e]; }
    int base[4] = {0, 0, 0, 0};
    for (int start = 0; start < T_TOK; start += 1024) {
        int t = start + tid;
        unsigned v = __float_as_uint(g_wtop0[t]) - 0x3F000000u;
        if (v > 0x7FFFFFu) v = 0x7FFFFFu;
        int mk = g_mask[t];
        int r[3];
        bool gt[3], eq[3];
#pragma unroll
        for (int e = 0; e < 3; e++) {
            bool m = ((mk >> e) & 1) != 0;
            eq[e] = m && (v == pre[e]);
            gt[e] = m && (v > pre[e]);
            unsigned bal = __ballot_sync(0xffffffffu, eq[e]);
            r[e] = __popc(bal & ((1u << lane) - 1u));
            if (lane == 0) warpcnt[wid][e] = __popc(bal);
        }
        __syncthreads();
        int wb[3] = {0, 0, 0}, ct[3] = {0, 0, 0};
        for (int w = 0; w < 32; w++) {
#pragma unroll
            for (int e = 0; e < 3; e++) {
                int c = warpcnt[w][e];
                if (w < wid) wb[e] += c;
                ct[e] += c;
            }
        }
        int selbits = 0;
#pragma unroll
        for (int e = 0; e < 3; e++) {
            int rank = base[e] + wb[e] + r[e];
            if (gt[e] || (eq[e] && rank < tt[e])) selbits |= 1 << e;
        }
        g_w[t] = (unsigned char)selbits;
        int wmul = __popc((unsigned)selbits);
        bool has = wmul > 0;
        unsigned bal3 = __ballot_sync(0xffffffffu, has);
        int r3 = __popc(bal3 & ((1u << lane) - 1u));
        if (lane == 0) warpcnt[wid][3] = __popc(bal3);
        __syncthreads();
        int wb3 = 0, ct3 = 0;
        for (int w = 0; w < 32; w++) {
            int c = warpcnt[w][3];
            if (w < wid) wb3 += c;
            ct3 += c;
        }
        if (has) g_list[base[3] + wb3 + r3] = t | (wmul << 20);
        base[0] += ct[0]; base[1] += ct[1]; base[2] += ct[2]; base[3] += ct3;
        __syncthreads();
    }
    if (tid == 0) g_listcnt = base[3];
}

// ---------------- weighted column sums of patches (bag + 3 expert sums), deterministic ----------------
__global__ __launch_bounds__(512) void msum_kernel() {
    int blk = blockIdx.x;          // 128 blocks
    int p = threadIdx.x;           // 512 columns
    int t0 = blk * 512;
    float sb = 0.f, s0 = 0.f, s1 = 0.f, s2 = 0.f;
    for (int i = 0; i < 512; i++) {
        int t = t0 + i;
        float v = g_patches[(size_t)t * 512 + p];
        sb += v;
        int w = g_w[t];
        if (w & 1) s0 += v;
        if (w & 2) s1 += v;
        if (w & 4) s2 += v;
    }
    float* base = &g_ms_part[blk * 4 * 512];
    base[p] = sb;
    base[512 + p] = s0;
    base[1024 + p] = s1;
    base[1536 + p] = s2;
}

// grid 4 (one per array), 512 threads; deterministic fixed-order reduce
__global__ __launch_bounds__(512) void msum_reduce_kernel() {
    int a = blockIdx.x;            // 0=bag,1..3=experts
    int p = threadIdx.x;
    float s = 0.f;
    for (int b = 0; b < 128; b++) s += g_ms_part[b * 2048 + a * 512 + p];
    if (a == 0) g_bag[p] = s;
    else g_ms[a - 1][p] = s;
}

// ---------------- block reduction helper (512 threads) ----------------
__device__ float blockReduce512(float v, float* red) {
    int tid = threadIdx.x;
    red[tid] = v;
    __syncthreads();
    for (int s = 256; s > 0; s >>= 1) {
        if (tid < s) red[tid] += red[tid + s];
        __syncthreads();
    }
    float r = red[0];
    __syncthreads();
    return r;
}

// ---------------- trans1 outputs + expert CE losses + distribute ----------------
__global__ __launch_bounds__(512) void finalize1_kernel(const float* __restrict__ W_cls1,
                                                        const float* __restrict__ W_clf,
                                                        float* __restrict__ out) {
    __shared__ float red[512];
    int p = threadIdx.x;
    float bagmean = g_bag[p] * (1.0f / 65536.0f);
    float yl0 = blockReduce512(bagmean * W_cls1[2 * p], red);
    float yl1 = blockReduce512(bagmean * W_cls1[2 * p + 1], red);
    float l[3][3];
    for (int e = 0; e < 3; e++) {
        int nd = g_nums[e];
        if (nd < 1) nd = 1;
        float mf = g_ms[e][p] / (float)nd;
        for (int c = 0; c < 3; c++)
            l[e][c] = blockReduce512(mf * W_clf[(e * 512 + p) * 3 + c], red);
    }
    if (p == 0) {
        out[3] = yl0;
        out[4] = yl1;
        float m = fmaxf(yl0, yl1);
        float e0 = expf(yl0 - m), e1 = expf(yl1 - m);
        float s = e0 + e1;
        out[5] = e0 / s;
        out[6] = e1 / s;
        out[7] = (yl1 > yl0) ? 1.f : 0.f;
        float loss = 0.f;
        for (int e = 0; e < 2; e++) {
            float m3 = fmaxf(l[e][0], fmaxf(l[e][1], l[e][2]));
            float lse = logf(expf(l[e][0] - m3) + expf(l[e][1] - m3) + expf(l[e][2] - m3));
            loss += -(l[e][e] - m3 - lse);
        }
        out[131080] = loss;
        out[131081] = 65536.f;
        out[131082] = (float)g_nums[0];
        out[131083] = (float)g_nums[1];
        out[131084] = (float)g_nums[2];
    }
}

// grid 4, 512 threads: col = blk*128 + (tid&127), each thread sums 128 rowtiles; fixed-order combine
__global__ __launch_bounds__(512) void acc_reduce_kernel() {
    __shared__ float red[512];
    int tid = threadIdx.x;
    int col = blockIdx.x * 128 + (tid & 127);
    int seg = tid >> 7;               // 0..3
    float s = 0.f;
    for (int rt = seg; rt < 512; rt += 4) s += g_acc_part[rt * 512 + col];
    red[tid] = s;
    __syncthreads();
    if (seg == 0)
        g_acc[col] = red[tid] + red[tid + 128] + red[tid + 256] + red[tid + 384];
}

// ---------------- aggregated classifier outputs ----------------
__global__ __launch_bounds__(512) void finalize2_kernel(const float* __restrict__ W_acls,
                                                        float* __restrict__ out) {
    __shared__ float red[512];
    int p = threadIdx.x;
    float tn = (float)(g_nums[0] + g_nums[1] + g_nums[2]);
    float d = fmaxf(tn, 1.0f);
    float a = g_acc[p] / d;
    float el0 = blockReduce512(a * W_acls[2 * p], red);
    float el1 = blockReduce512(a * W_acls[2 * p + 1], red);
    if (p == 0) {
        out[0] = el0;
        out[1] = el1;
        out[2] = (el1 > el0) ? 1.f : 0.f;
    }
}

// ---------------- launch ----------------
extern "C" void kernel_launch(void* const* d_in, const int* in_sizes, int n_in,
                              void* d_out, int out_size) {
    (void)in_sizes; (void)n_in; (void)out_size;
    const float* hidden = (const float*)d_in[0];
    const float* W_t1   = (const float*)d_in[1];
    const float* W_cls1 = (const float*)d_in[2];
    const float* Wg0    = (const float*)d_in[3];
    const float* Wg1    = (const float*)d_in[4];
    const float* Wg2    = (const float*)d_in[5];
    const float* W_clf  = (const float*)d_in[6];
    const float* W_a1   = (const float*)d_in[7];
    const float* W_acls = (const float*)d_in[8];
    float* out = (float*)d_out;

    cudaFuncSetAttribute(gemm1_mma_kernel, cudaFuncAttributeMaxDynamicSharedMemorySize, 65536);
    cudaFuncSetAttribute(gemm2_mma_kernel, cudaFuncAttributeMaxDynamicSharedMemorySize, 65536);

    zero_kernel<<<512, 256>>>();
    prep_kernel<<<4096, 256>>>(W_t1, 32, 0);
    prep_kernel<<<2048, 256>>>(W_a1, 16, 1);
    prepA_kernel<<<32768, 256>>>(hidden);

    dim3 g1(4, 512);
    gemm1_mma_kernel<<<g1, 256, 65536>>>();

    router_kernel<<<8192, 256>>>(Wg0, Wg1, Wg2, out + 8);

    hist_kernel<<<64, 256>>>(0);
    find_kernel<<<1, 256>>>(0);
    hist_kernel<<<64, 256>>>(1);
    find_kernel<<<1, 256>>>(1);
    hist_kernel<<<64, 256>>>(2);
    find_kernel<<<1, 256>>>(2);

    select_kernel<<<1, 1024>>>();

    msum_kernel<<<128, 512>>>();
    msum_reduce_kernel<<<4, 512>>>();
    finalize1_kernel<<<1, 512>>>(W_cls1, W_clf, out);

    dim3 g2(4, 512);
    gemm2_mma_kernel<<<g2, 256, 65536>>>();
    acc_reduce_kernel<<<4, 512>>>();
    finalize2_kernel<<<1, 512>>>(W_acls, out);
}